// round 1
// baseline (speedup 1.0000x reference)
#include <cuda_runtime.h>

// Problem constants
#define BATCH   8
#define NPTS    16384
#define BN      (BATCH * NPTS)     // 131072 points
#define TILE    64                 // points per CTA
#define NTILES  (BN / TILE)        // 2048
#define THREADS 256

// Shared memory layout (floats)
#define OFF_IO   0                 // 64x128 = 8192   (input tile / conv2 out / o1)
#define OFF_CAT  8192              // 64x256 = 16384  (concat buf / f0 / pool table / o2)
#define OFF_MID  24576             // 64x64  = 4096   (conv1 out)
#define OFF_WT   28672             // up to 128x129 = 16512 (transposed weight chunk)
#define WT_FLOATS 16512
#define SMEM_FLOATS (OFF_WT + WT_FLOATS)          // 45184
#define SMEM_BYTES  (SMEM_FLOATS * 4 + 128 * 4)   // + 2x64 cluster ids = 181248 B

// Global scratch (allocation-free: __device__ globals)
__device__ float g_bufA[BN * 128];            // 64 MB
__device__ float g_bufB[BN * 128];            // 64 MB
__device__ float g_pool[3 * BATCH * 64 * 128];// pool tables, stride 64 clusters

__global__ void init_kernel(float* __restrict__ out) {
    int i = blockIdx.x * blockDim.x + threadIdx.x;
    if (i < 3 * BATCH * 64 * 128) g_pool[i] = 0.0f;
    if (i < BATCH * 128) out[i] = 0.0f;
}

// out[p][j] = relu(bias[j] + sum_k in[p][k] * W[j][k])
// sIn: [64][CIN] (ld_in), gW: [COUT][CIN] row-major in gmem, sOut: [64][COUT] (ld_out)
// Weights are staged transposed into sWT[k][j] with +1 pad (conflict-free), in K-chunks of 128.
// Thread (tm=tid>>5, lane=tid&31) computes rows tm*8..tm*8+7, cols lane+32c.
template<int NC>
__device__ __forceinline__ void gemm_relu(
    const float* __restrict__ sIn, int ld_in, int CIN,
    const float* __restrict__ gW, const float* __restrict__ gB,
    float* __restrict__ sOut, int ld_out, float* __restrict__ sWT)
{
    const int COUT = NC * 32;
    const int tid  = threadIdx.x;
    const int tm   = tid >> 5;
    const int lane = tid & 31;

    float acc[8][NC];
#pragma unroll
    for (int r = 0; r < 8; r++)
#pragma unroll
        for (int c = 0; c < NC; c++) acc[r][c] = 0.0f;

    for (int k0 = 0; k0 < CIN; k0 += 128) {
        const int kc = (CIN - k0 < 128) ? (CIN - k0) : 128;
        __syncthreads();  // previous users of sWT done; prior stage outputs visible
        for (int idx = tid; idx < kc * COUT; idx += THREADS) {
            int j = idx / kc;
            int k = idx - j * kc;
            sWT[k * (COUT + 1) + j] = gW[j * CIN + k0 + k];
        }
        __syncthreads();
        const float* sI = sIn + k0;
        for (int k = 0; k < kc; k++) {
            float bb[NC];
#pragma unroll
            for (int c = 0; c < NC; c++) bb[c] = sWT[k * (COUT + 1) + lane + 32 * c];
#pragma unroll
            for (int r = 0; r < 8; r++) {
                float a = sI[(tm * 8 + r) * ld_in + k];
#pragma unroll
                for (int c = 0; c < NC; c++) acc[r][c] = fmaf(a, bb[c], acc[r][c]);
            }
        }
    }

    float bias[NC];
#pragma unroll
    for (int c = 0; c < NC; c++) bias[c] = gB[lane + 32 * c];
#pragma unroll
    for (int r = 0; r < 8; r++) {
        int row = tm * 8 + r;
#pragma unroll
        for (int c = 0; c < NC; c++)
            sOut[row * ld_out + lane + 32 * c] = fmaxf(acc[r][c] + bias[c], 0.0f);
    }
}

// SMEM pre-reduced segment max, then flush to global table.
// s_out: [64][128] (post-relu, >=0). s_pool scratch >= nc*128 floats.
__device__ __forceinline__ void pool_scatter(
    const float* __restrict__ s_out, float* __restrict__ s_pool,
    const int* __restrict__ s_cl, int nc, int b, float* __restrict__ gpool)
{
    const int tid = threadIdx.x;
    for (int t = tid; t < nc * 128; t += THREADS) s_pool[t] = 0.0f;
    __syncthreads();  // also makes s_out (conv2 epilogue) visible
    for (int t = tid; t < TILE * 128; t += THREADS) {
        int p = t >> 7, c = t & 127;
        atomicMax((int*)&s_pool[s_cl[p] * 128 + c], __float_as_int(s_out[t]));
    }
    __syncthreads();
    for (int t = tid; t < nc * 128; t += THREADS) {
        float v = s_pool[t];
        if (v > 0.0f)
            atomicMax((int*)&gpool[b * (64 * 128) + t], __float_as_int(v));
    }
}

// K0: x(28) -> mlp_in(256) -> conv1_0(64) -> conv2_0(128); write F; pool0 atomics
__global__ void __launch_bounds__(THREADS)
k0_kernel(const float* __restrict__ x, const int* __restrict__ clusters,
          const float* __restrict__ w_in, const float* __restrict__ b_in,
          const float* __restrict__ w1, const float* __restrict__ b1,
          const float* __restrict__ w2, const float* __restrict__ b2)
{
    extern __shared__ float sm[];
    float* s_io  = sm + OFF_IO;
    float* s_cat = sm + OFF_CAT;
    float* s_mid = sm + OFF_MID;
    float* s_wT  = sm + OFF_WT;
    int*   s_cl  = (int*)(sm + SMEM_FLOATS);

    const int tid = threadIdx.x;
    const int P0  = blockIdx.x * TILE;
    const int b   = P0 / NPTS;

    for (int t = tid; t < TILE * 28; t += THREADS) s_io[t] = x[P0 * 28 + t];
    if (tid < TILE) s_cl[tid] = clusters[P0 + tid];   // clusters[0]

    gemm_relu<8>(s_io, 28, 28, w_in, b_in, s_cat, 256, s_wT);   // 28 -> 256
    gemm_relu<2>(s_cat, 256, 256, w1, b1, s_mid, 64, s_wT);     // 256 -> 64
    gemm_relu<4>(s_mid, 64, 64, w2, b2, s_io, 128, s_wT);       // 64 -> 128
    __syncthreads();

    for (int t = tid; t < TILE * 128; t += THREADS) g_bufA[P0 * 128 + t] = s_io[t];
    pool_scatter(s_io, s_cat, s_cl, 16, b, g_pool);
}

// K1/K2: fin(128)+pool_in gather -> conv3(128) | concat(256) -> conv1(64) -> conv2(128)
//        write fout; pool_out atomics
__global__ void __launch_bounds__(THREADS)
mid_kernel(const float* __restrict__ fin, float* __restrict__ fout,
           const int* __restrict__ cl_in, const int* __restrict__ cl_out,
           const float* __restrict__ gpool_in, float* __restrict__ gpool_out, int nc_out,
           const float* __restrict__ w3, const float* __restrict__ b3,
           const float* __restrict__ w1, const float* __restrict__ b1,
           const float* __restrict__ w2, const float* __restrict__ b2)
{
    extern __shared__ float sm[];
    float* s_io  = sm + OFF_IO;
    float* s_cat = sm + OFF_CAT;
    float* s_mid = sm + OFF_MID;
    float* s_wT  = sm + OFF_WT;
    int*   s_cli = (int*)(sm + SMEM_FLOATS);
    int*   s_clo = s_cli + 64;

    const int tid = threadIdx.x;
    const int P0  = blockIdx.x * TILE;
    const int b   = P0 / NPTS;

    for (int t = tid; t < TILE * 128; t += THREADS) s_io[t] = fin[P0 * 128 + t];
    if (tid < TILE) s_cli[tid] = cl_in[P0 + tid];
    if (tid < TILE) s_clo[tid] = cl_out[P0 + tid];
    __syncthreads();

    // gather pooled features into concat cols 128..255
    for (int t = tid; t < TILE * 128; t += THREADS) {
        int p = t >> 7, c = t & 127;
        s_cat[p * 256 + 128 + c] = gpool_in[(b * 64 + s_cli[p]) * 128 + c];
    }

    gemm_relu<4>(s_io, 128, 128, w3, b3, s_cat, 256, s_wT);   // conv3 -> cols 0..127
    gemm_relu<2>(s_cat, 256, 256, w1, b1, s_mid, 64, s_wT);   // 256 -> 64
    gemm_relu<4>(s_mid, 64, 64, w2, b2, s_io, 128, s_wT);     // 64 -> 128
    __syncthreads();

    for (int t = tid; t < TILE * 128; t += THREADS) fout[P0 * 128 + t] = s_io[t];
    pool_scatter(s_io, s_cat, s_clo, nc_out, b, gpool_out);
}

// K3: fin(128)+pool2 gather -> conv3_2 | concat -> out1(128) -> out2(128) -> per-batch max
__global__ void __launch_bounds__(THREADS)
final_kernel(const float* __restrict__ fin, const int* __restrict__ cl_in,
             const float* __restrict__ gpool_in,
             const float* __restrict__ w3, const float* __restrict__ b3,
             const float* __restrict__ wo1, const float* __restrict__ bo1,
             const float* __restrict__ wo2, const float* __restrict__ bo2,
             float* __restrict__ out)
{
    extern __shared__ float sm[];
    float* s_io  = sm + OFF_IO;
    float* s_cat = sm + OFF_CAT;
    float* s_wT  = sm + OFF_WT;
    int*   s_cli = (int*)(sm + SMEM_FLOATS);

    const int tid = threadIdx.x;
    const int P0  = blockIdx.x * TILE;
    const int b   = P0 / NPTS;

    for (int t = tid; t < TILE * 128; t += THREADS) s_io[t] = fin[P0 * 128 + t];
    if (tid < TILE) s_cli[tid] = cl_in[P0 + tid];
    __syncthreads();

    for (int t = tid; t < TILE * 128; t += THREADS) {
        int p = t >> 7, c = t & 127;
        s_cat[p * 256 + 128 + c] = gpool_in[(b * 64 + s_cli[p]) * 128 + c];
    }

    gemm_relu<4>(s_io, 128, 128, w3, b3, s_cat, 256, s_wT);    // conv3 -> cols 0..127
    gemm_relu<4>(s_cat, 256, 256, wo1, bo1, s_io, 128, s_wT);  // out1
    gemm_relu<4>(s_io, 128, 128, wo2, bo2, s_cat, 128, s_wT);  // out2 -> s_cat [64][128]
    __syncthreads();

    if (tid < 128) {
        float m = 0.0f;  // post-relu values >= 0
        for (int p = 0; p < TILE; p++) m = fmaxf(m, s_cat[p * 128 + tid]);
        atomicMax((int*)&out[b * 128 + tid], __float_as_int(m));
    }
}

extern "C" void kernel_launch(void* const* d_in, const int* in_sizes, int n_in,
                              void* d_out, int out_size)
{
    const float* x    = (const float*)d_in[0];
    const int*   cl   = (const int*)  d_in[1];
    const float* w_in = (const float*)d_in[2];
    const float* b_in = (const float*)d_in[3];
    const float* w1   = (const float*)d_in[4];
    const float* b1   = (const float*)d_in[5];
    const float* w2   = (const float*)d_in[6];
    const float* b2   = (const float*)d_in[7];
    const float* w3   = (const float*)d_in[8];
    const float* b3   = (const float*)d_in[9];
    const float* wo1  = (const float*)d_in[10];
    const float* bo1  = (const float*)d_in[11];
    const float* wo2  = (const float*)d_in[12];
    const float* bo2  = (const float*)d_in[13];
    float* out = (float*)d_out;

    void *pa_, *pb_, *pp_;
    cudaGetSymbolAddress(&pa_, g_bufA);
    cudaGetSymbolAddress(&pb_, g_bufB);
    cudaGetSymbolAddress(&pp_, g_pool);
    float* pA = (float*)pa_;
    float* pB = (float*)pb_;
    float* pP = (float*)pp_;

    cudaFuncSetAttribute(k0_kernel,    cudaFuncAttributeMaxDynamicSharedMemorySize, SMEM_BYTES);
    cudaFuncSetAttribute(mid_kernel,   cudaFuncAttributeMaxDynamicSharedMemorySize, SMEM_BYTES);
    cudaFuncSetAttribute(final_kernel, cudaFuncAttributeMaxDynamicSharedMemorySize, SMEM_BYTES);

    const int PSTRIDE = BATCH * 64 * 128;  // one pool table

    init_kernel<<<(3 * PSTRIDE + 255) / 256, 256>>>(out);

    k0_kernel<<<NTILES, THREADS, SMEM_BYTES>>>(x, cl, w_in, b_in, w1, b1, w2, b2);

    mid_kernel<<<NTILES, THREADS, SMEM_BYTES>>>(
        pA, pB, cl, cl + BN, pP, pP + PSTRIDE, 32,
        w3, b3,
        w1 + 64 * 256, b1 + 64,
        w2 + 128 * 64, b2 + 128);

    mid_kernel<<<NTILES, THREADS, SMEM_BYTES>>>(
        pB, pA, cl + BN, cl + 2 * BN, pP + PSTRIDE, pP + 2 * PSTRIDE, 64,
        w3 + 128 * 128, b3 + 128,
        w1 + 2 * 64 * 256, b1 + 2 * 64,
        w2 + 2 * 128 * 64, b2 + 2 * 128);

    final_kernel<<<NTILES, THREADS, SMEM_BYTES>>>(
        pA, cl + 2 * BN, pP + 2 * PSTRIDE,
        w3 + 2 * 128 * 128, b3 + 2 * 128,
        wo1, bo1, wo2, bo2, out);
}

// round 2
// speedup vs baseline: 1.6783x; 1.6783x over previous
#include <cuda_runtime.h>
#include <cuda_bf16.h>

#define BATCH   8
#define NPTS    16384
#define BN      (BATCH * NPTS)     // 131072 points
#define TILE    64                 // points per CTA
#define NTILES  (BN / TILE)        // 2048
#define THREADS 256

// ---------------- smem layout (units: bf16 elements) ----------------
// activation planes (hi & lo), padded rows (+8 bf16) for conflict-free frag LDS
#define LD_CAT 264                 // 256 + 8
#define LD_IO  136                 // 128 + 8
#define LD_MID 72                  // 64 + 8
#define CAT_H  0
#define CAT_L  (CAT_H + 64*LD_CAT)          // 16896
#define IO_H   (CAT_L + 64*LD_CAT)          // 33792
#define IO_L   (IO_H  + 64*LD_IO)           // 42496
#define MID_H  (IO_L  + 64*LD_IO)           // 51200
#define MID_L  (MID_H + 64*LD_MID)          // 55808
#define WS_H   (MID_L + 64*LD_MID)          // 60416  (weight chunk hi, up to 256*40)
#define WS_L   (WS_H + 10240)               // 70656
#define SM_BF16 (WS_L + 10240)              // 80896 bf16
#define SMEM_BYTES (SM_BF16*2 + 512)        // + 128 ints for cluster ids

// ---------------- global scratch (allocation-free) ----------------
__device__ unsigned g_featA[BN * 128];          // packed (hi | lo<<16)
__device__ unsigned g_featB[BN * 128];
__device__ float    g_pool[3 * BATCH * 64 * 128];
__device__ __nv_bfloat16 g_wh[180224];
__device__ __nv_bfloat16 g_wl[180224];

// weight offsets inside g_wh/g_wl (padded-K layout [COUT][Kpad])
#define OFF_WIN 0        // 256 x 32   (cin 28 zero-padded)
#define OFF_W1  8192     // 192 x 256  (3 blocks of 64x256)
#define OFF_W2  57344    // 384 x 64
#define OFF_W3  81920    // 384 x 128
#define OFF_WO1 131072   // 128 x 256
#define OFF_WO2 163840   // 128 x 128

// ---------------- init / convert kernels ----------------
__global__ void init_kernel(float* __restrict__ out) {
    int i = blockIdx.x * blockDim.x + threadIdx.x;
    if (i < 3 * BATCH * 64 * 128) g_pool[i] = 0.0f;
    if (i < BATCH * 128) out[i] = 0.0f;
}

__global__ void convert_w(const float* __restrict__ src,
                          __nv_bfloat16* __restrict__ dh, __nv_bfloat16* __restrict__ dl,
                          int rows, int cin, int kpad) {
    int i = blockIdx.x * blockDim.x + threadIdx.x;
    if (i >= rows * kpad) return;
    int r = i / kpad, k = i - r * kpad;
    float v = (k < cin) ? src[r * cin + k] : 0.0f;
    __nv_bfloat16 h = __float2bfloat16(v);
    dh[i] = h;
    dl[i] = __float2bfloat16(v - __bfloat162float(h));
}

// ---------------- mma helpers ----------------
__device__ __forceinline__ void mma_bf16(float c[4], const unsigned a[4],
                                         unsigned b0, unsigned b1) {
    asm volatile(
        "mma.sync.aligned.m16n8k16.row.col.f32.bf16.bf16.f32 "
        "{%0,%1,%2,%3}, {%4,%5,%6,%7}, {%8,%9}, {%0,%1,%2,%3};"
        : "+f"(c[0]), "+f"(c[1]), "+f"(c[2]), "+f"(c[3])
        : "r"(a[0]), "r"(a[1]), "r"(a[2]), "r"(a[3]), "r"(b0), "r"(b1));
}
__device__ __forceinline__ unsigned lds_u32(const __nv_bfloat16* p) {
    return *reinterpret_cast<const unsigned*>(p);
}
__device__ __forceinline__ unsigned pack2(__nv_bfloat16 x, __nv_bfloat16 y) {
    unsigned u = ((unsigned)__bfloat16_as_ushort(y) << 16) | (unsigned)__bfloat16_as_ushort(x);
    return u;
}

// ---------------- fused GEMM + bias + ReLU + bf16-split writeback ----------------
// C[64][COUT] = relu(A[64][K] * W^T + bias); A,C as hi/lo bf16 planes in smem.
// Split-bf16: acc += Ah*Wh + Al*Wh + Ah*Wl (fp32 accumulate).
// 8 warps = 2 m-groups (32 rows) x 4 n-groups (COUT/4 cols).
template<int NT, int KW>   // COUT = NT*32 ; KW = padded K (mult of 16)
__device__ void gemm_relu(__nv_bfloat16* sm,
                          int aH, int aL, int ldA,
                          const __nv_bfloat16* __restrict__ gWh,
                          const __nv_bfloat16* __restrict__ gWl,
                          const float* __restrict__ gBias,
                          int cH, int cL, int ldC)
{
    constexpr int COUT = NT * 32;
    constexpr int KC   = (KW < 64) ? KW : 64;
    constexpr int LDW  = KC + 8;
    const int tid  = threadIdx.x;
    const int w    = tid >> 5;
    const int lane = tid & 31;
    const int g    = lane >> 2;   // 0..7
    const int t    = lane & 3;    // 0..3
    const int mg   = w & 1;       // m-group (32 rows)
    const int ng   = w >> 1;      // n-group (0..3)

    __nv_bfloat16* sWh = sm + WS_H;
    __nv_bfloat16* sWl = sm + WS_L;
    const __nv_bfloat16* sAh = sm + aH;
    const __nv_bfloat16* sAl = sm + aL;

    float acc[2][NT][4];
#pragma unroll
    for (int mt = 0; mt < 2; mt++)
#pragma unroll
        for (int nt = 0; nt < NT; nt++)
#pragma unroll
            for (int i = 0; i < 4; i++) acc[mt][nt][i] = 0.0f;

#pragma unroll
    for (int kc0 = 0; kc0 < KW; kc0 += KC) {
        __syncthreads();   // prior stage finished with sW / epilogue visible
        // stage weight chunk [COUT][KC] (bf16 pairs as u32)
        for (int idx = tid; idx < COUT * (KC / 2); idx += THREADS) {
            int row = idx / (KC / 2);
            int kk  = (idx - row * (KC / 2)) * 2;
            *(unsigned*)(sWh + row * LDW + kk) = *(const unsigned*)(gWh + row * KW + kc0 + kk);
            *(unsigned*)(sWl + row * LDW + kk) = *(const unsigned*)(gWl + row * KW + kc0 + kk);
        }
        __syncthreads();
#pragma unroll
        for (int ks = 0; ks < KC; ks += 16) {
            unsigned ah[2][4], al[2][4];
#pragma unroll
            for (int mt = 0; mt < 2; mt++) {
                int r0 = mg * 32 + mt * 16;
                const __nv_bfloat16* ph = sAh + (r0 + g) * ldA + kc0 + ks + 2 * t;
                const __nv_bfloat16* pl = sAl + (r0 + g) * ldA + kc0 + ks + 2 * t;
                ah[mt][0] = lds_u32(ph);
                ah[mt][1] = lds_u32(ph + 8 * ldA);
                ah[mt][2] = lds_u32(ph + 8);
                ah[mt][3] = lds_u32(ph + 8 * ldA + 8);
                al[mt][0] = lds_u32(pl);
                al[mt][1] = lds_u32(pl + 8 * ldA);
                al[mt][2] = lds_u32(pl + 8);
                al[mt][3] = lds_u32(pl + 8 * ldA + 8);
            }
#pragma unroll
            for (int nt = 0; nt < NT; nt++) {
                int n0 = ng * (NT * 8) + nt * 8;
                const __nv_bfloat16* pwh = sWh + (n0 + g) * LDW + ks + 2 * t;
                const __nv_bfloat16* pwl = sWl + (n0 + g) * LDW + ks + 2 * t;
                unsigned bh0 = lds_u32(pwh), bh1 = lds_u32(pwh + 8);
                unsigned bl0 = lds_u32(pwl), bl1 = lds_u32(pwl + 8);
#pragma unroll
                for (int mt = 0; mt < 2; mt++) {
                    mma_bf16(acc[mt][nt], ah[mt], bh0, bh1);
                    mma_bf16(acc[mt][nt], al[mt], bh0, bh1);
                    mma_bf16(acc[mt][nt], ah[mt], bl0, bl1);
                }
            }
        }
    }

    // epilogue: bias + relu + bf16 split, packed u32 stores
    __nv_bfloat16* sCh = sm + cH;
    __nv_bfloat16* sCl = sm + cL;
#pragma unroll
    for (int nt = 0; nt < NT; nt++) {
        int n0 = ng * (NT * 8) + nt * 8 + 2 * t;
        float bb0 = gBias[n0], bb1 = gBias[n0 + 1];
#pragma unroll
        for (int mt = 0; mt < 2; mt++) {
            int r = mg * 32 + mt * 16 + g;
            float v0 = fmaxf(acc[mt][nt][0] + bb0, 0.0f);
            float v1 = fmaxf(acc[mt][nt][1] + bb1, 0.0f);
            float v2 = fmaxf(acc[mt][nt][2] + bb0, 0.0f);
            float v3 = fmaxf(acc[mt][nt][3] + bb1, 0.0f);
            __nv_bfloat16 h0 = __float2bfloat16(v0), h1 = __float2bfloat16(v1);
            __nv_bfloat16 h2 = __float2bfloat16(v2), h3 = __float2bfloat16(v3);
            __nv_bfloat16 l0 = __float2bfloat16(v0 - __bfloat162float(h0));
            __nv_bfloat16 l1 = __float2bfloat16(v1 - __bfloat162float(h1));
            __nv_bfloat16 l2 = __float2bfloat16(v2 - __bfloat162float(h2));
            __nv_bfloat16 l3 = __float2bfloat16(v3 - __bfloat162float(h3));
            *(unsigned*)(sCh + r * ldC + n0)       = pack2(h0, h1);
            *(unsigned*)(sCh + (r + 8) * ldC + n0) = pack2(h2, h3);
            *(unsigned*)(sCl + r * ldC + n0)       = pack2(l0, l1);
            *(unsigned*)(sCl + (r + 8) * ldC + n0) = pack2(l2, l3);
        }
    }
}

// ---------------- feature store + segment-max pool ----------------
__device__ void store_and_pool(__nv_bfloat16* sm, const int* s_cl, int nc, int b,
                               unsigned* __restrict__ gfeat, float* __restrict__ gpool,
                               int P0)
{
    const int tid = threadIdx.x;
    for (int i = tid; i < TILE * 128; i += THREADS) {
        int p = i >> 7, c = i & 127;
        unsigned h = (unsigned)__bfloat16_as_ushort(sm[IO_H + p * LD_IO + c]);
        unsigned l = (unsigned)__bfloat16_as_ushort(sm[IO_L + p * LD_IO + c]);
        gfeat[(size_t)(P0 + p) * 128 + c] = h | (l << 16);
    }
    float* spool = (float*)sm;   // overlays CAT region (free now); <= 32KB
    for (int i = tid; i < nc * 128; i += THREADS) spool[i] = 0.0f;
    __syncthreads();
    for (int i = tid; i < TILE * 128; i += THREADS) {
        int p = i >> 7, c = i & 127;
        float v = __bfloat162float(sm[IO_H + p * LD_IO + c]) +
                  __bfloat162float(sm[IO_L + p * LD_IO + c]);
        atomicMax((int*)&spool[s_cl[p] * 128 + c], __float_as_int(v));
    }
    __syncthreads();
    for (int i = tid; i < nc * 128; i += THREADS) {
        float v = spool[i];
        if (v > 0.0f)
            atomicMax((int*)&gpool[b * (64 * 128) + i], __float_as_int(v));
    }
}

// ---------------- K0: x(28) -> 256 -> 64 -> 128 ; write feat; pool0 ----------------
__global__ void __launch_bounds__(THREADS)
k0_kernel(const float* __restrict__ x, const int* __restrict__ clusters,
          const float* __restrict__ b_in, const float* __restrict__ b1,
          const float* __restrict__ b2,
          const __nv_bfloat16* __restrict__ wh, const __nv_bfloat16* __restrict__ wl,
          unsigned* __restrict__ gfeat, float* __restrict__ gpool)
{
    extern __shared__ __nv_bfloat16 sm[];
    int* s_cl = (int*)(sm + SM_BF16);
    const int tid = threadIdx.x;
    const int P0  = blockIdx.x * TILE;
    const int b   = P0 / NPTS;

    for (int i = tid; i < TILE * 32; i += THREADS) {
        int p = i >> 5, k = i & 31;
        float v = (k < 28) ? x[(size_t)(P0 + p) * 28 + k] : 0.0f;
        __nv_bfloat16 h = __float2bfloat16(v);
        sm[MID_H + p * LD_MID + k] = h;
        sm[MID_L + p * LD_MID + k] = __float2bfloat16(v - __bfloat162float(h));
    }
    if (tid < TILE) s_cl[tid] = clusters[P0 + tid];

    gemm_relu<8, 32>(sm, MID_H, MID_L, LD_MID, g_wh + OFF_WIN, g_wl + OFF_WIN, b_in, CAT_H, CAT_L, LD_CAT);
    gemm_relu<2, 256>(sm, CAT_H, CAT_L, LD_CAT, wh, wl, b1, MID_H, MID_L, LD_MID);
    gemm_relu<4, 64>(sm, MID_H, MID_L, LD_MID, g_wh + OFF_W2, g_wl + OFF_W2, b2, IO_H, IO_L, LD_IO);
    __syncthreads();

    store_and_pool(sm, s_cl, 16, b, gfeat, gpool, P0);
}

// ---------------- mid blocks: feat(128)+pool -> conv3|concat -> 64 -> 128 ----------------
__global__ void __launch_bounds__(THREADS)
mid_kernel(const unsigned* __restrict__ fin, unsigned* __restrict__ fout,
           const int* __restrict__ cl_in, const int* __restrict__ cl_out,
           const float* __restrict__ gpool_in, float* __restrict__ gpool_out, int nc_out,
           const __nv_bfloat16* __restrict__ wh3, const __nv_bfloat16* __restrict__ wl3,
           const float* __restrict__ b3,
           const __nv_bfloat16* __restrict__ wh1, const __nv_bfloat16* __restrict__ wl1,
           const float* __restrict__ b1,
           const __nv_bfloat16* __restrict__ wh2, const __nv_bfloat16* __restrict__ wl2,
           const float* __restrict__ b2)
{
    extern __shared__ __nv_bfloat16 sm[];
    int* s_cl = (int*)(sm + SM_BF16);
    const int tid = threadIdx.x;
    const int P0  = blockIdx.x * TILE;
    const int b   = P0 / NPTS;

    for (int i = tid; i < TILE * 128; i += THREADS) {
        int p = i >> 7, c = i & 127;
        unsigned u = fin[(size_t)(P0 + p) * 128 + c];
        sm[IO_H + p * LD_IO + c] = __ushort_as_bfloat16((unsigned short)(u & 0xffff));
        sm[IO_L + p * LD_IO + c] = __ushort_as_bfloat16((unsigned short)(u >> 16));
    }
    if (tid < TILE) s_cl[tid] = cl_in[P0 + tid];
    else if (tid < 2 * TILE) s_cl[tid] = cl_out[P0 + tid - TILE];
    __syncthreads();

    // gather pooled features into concat cols 128..255 (bf16 split)
    for (int i = tid; i < TILE * 128; i += THREADS) {
        int p = i >> 7, c = i & 127;
        float v = gpool_in[(b * 64 + s_cl[p]) * 128 + c];
        __nv_bfloat16 h = __float2bfloat16(v);
        sm[CAT_H + p * LD_CAT + 128 + c] = h;
        sm[CAT_L + p * LD_CAT + 128 + c] = __float2bfloat16(v - __bfloat162float(h));
    }

    gemm_relu<4, 128>(sm, IO_H, IO_L, LD_IO, wh3, wl3, b3, CAT_H, CAT_L, LD_CAT);   // cols 0..127
    gemm_relu<2, 256>(sm, CAT_H, CAT_L, LD_CAT, wh1, wl1, b1, MID_H, MID_L, LD_MID);
    gemm_relu<4, 64>(sm, MID_H, MID_L, LD_MID, wh2, wl2, b2, IO_H, IO_L, LD_IO);
    __syncthreads();

    store_and_pool(sm, s_cl + TILE, nc_out, b, fout, gpool_out, P0);
}

// ---------------- final: conv3_2|concat -> out1 -> out2 -> global max ----------------
__global__ void __launch_bounds__(THREADS)
final_kernel(const unsigned* __restrict__ fin, const int* __restrict__ cl_in,
             const float* __restrict__ gpool_in,
             const __nv_bfloat16* __restrict__ wh3, const __nv_bfloat16* __restrict__ wl3,
             const float* __restrict__ b3,
             const float* __restrict__ bo1, const float* __restrict__ bo2,
             float* __restrict__ out)
{
    extern __shared__ __nv_bfloat16 sm[];
    int* s_cl = (int*)(sm + SM_BF16);
    const int tid = threadIdx.x;
    const int P0  = blockIdx.x * TILE;
    const int b   = P0 / NPTS;

    for (int i = tid; i < TILE * 128; i += THREADS) {
        int p = i >> 7, c = i & 127;
        unsigned u = fin[(size_t)(P0 + p) * 128 + c];
        sm[IO_H + p * LD_IO + c] = __ushort_as_bfloat16((unsigned short)(u & 0xffff));
        sm[IO_L + p * LD_IO + c] = __ushort_as_bfloat16((unsigned short)(u >> 16));
    }
    if (tid < TILE) s_cl[tid] = cl_in[P0 + tid];
    __syncthreads();

    for (int i = tid; i < TILE * 128; i += THREADS) {
        int p = i >> 7, c = i & 127;
        float v = gpool_in[(b * 64 + s_cl[p]) * 128 + c];
        __nv_bfloat16 h = __float2bfloat16(v);
        sm[CAT_H + p * LD_CAT + 128 + c] = h;
        sm[CAT_L + p * LD_CAT + 128 + c] = __float2bfloat16(v - __bfloat162float(h));
    }

    gemm_relu<4, 128>(sm, IO_H, IO_L, LD_IO, wh3, wl3, b3, CAT_H, CAT_L, LD_CAT);       // conv3
    gemm_relu<4, 256>(sm, CAT_H, CAT_L, LD_CAT, g_wh + OFF_WO1, g_wl + OFF_WO1, bo1, IO_H, IO_L, LD_IO);
    gemm_relu<4, 128>(sm, IO_H, IO_L, LD_IO, g_wh + OFF_WO2, g_wl + OFF_WO2, bo2, CAT_H, CAT_L, LD_CAT);
    __syncthreads();

    if (tid < 128) {
        float m = 0.0f;
        for (int p = 0; p < TILE; p++)
            m = fmaxf(m, __bfloat162float(sm[CAT_H + p * LD_CAT + tid]) +
                         __bfloat162float(sm[CAT_L + p * LD_CAT + tid]));
        atomicMax((int*)&out[b * 128 + tid], __float_as_int(m));
    }
}

extern "C" void kernel_launch(void* const* d_in, const int* in_sizes, int n_in,
                              void* d_out, int out_size)
{
    const float* x    = (const float*)d_in[0];
    const int*   cl   = (const int*)  d_in[1];
    const float* w_in = (const float*)d_in[2];
    const float* b_in = (const float*)d_in[3];
    const float* w1   = (const float*)d_in[4];
    const float* b1   = (const float*)d_in[5];
    const float* w2   = (const float*)d_in[6];
    const float* b2   = (const float*)d_in[7];
    const float* w3   = (const float*)d_in[8];
    const float* b3   = (const float*)d_in[9];
    const float* wo1  = (const float*)d_in[10];
    const float* bo1  = (const float*)d_in[11];
    const float* wo2  = (const float*)d_in[12];
    const float* bo2  = (const float*)d_in[13];
    float* out = (float*)d_out;

    void *pa_, *pb_, *pp_, *ph_, *pl_;
    cudaGetSymbolAddress(&pa_, g_featA);
    cudaGetSymbolAddress(&pb_, g_featB);
    cudaGetSymbolAddress(&pp_, g_pool);
    cudaGetSymbolAddress(&ph_, g_wh);
    cudaGetSymbolAddress(&pl_, g_wl);
    unsigned* fA = (unsigned*)pa_;
    unsigned* fB = (unsigned*)pb_;
    float* pP = (float*)pp_;
    __nv_bfloat16* wh = (__nv_bfloat16*)ph_;
    __nv_bfloat16* wl = (__nv_bfloat16*)pl_;

    cudaFuncSetAttribute(k0_kernel,    cudaFuncAttributeMaxDynamicSharedMemorySize, SMEM_BYTES);
    cudaFuncSetAttribute(mid_kernel,   cudaFuncAttributeMaxDynamicSharedMemorySize, SMEM_BYTES);
    cudaFuncSetAttribute(final_kernel, cudaFuncAttributeMaxDynamicSharedMemorySize, SMEM_BYTES);

    const int PSTRIDE = BATCH * 64 * 128;

    init_kernel<<<(3 * PSTRIDE + 255) / 256, 256>>>(out);
    convert_w<<<(256 * 32 + 255) / 256, 256>>>(w_in, wh + OFF_WIN, wl + OFF_WIN, 256, 28, 32);
    convert_w<<<(192 * 256 + 255) / 256, 256>>>(w1, wh + OFF_W1, wl + OFF_W1, 192, 256, 256);
    convert_w<<<(384 * 64 + 255) / 256, 256>>>(w2, wh + OFF_W2, wl + OFF_W2, 384, 64, 64);
    convert_w<<<(384 * 128 + 255) / 256, 256>>>(w3, wh + OFF_W3, wl + OFF_W3, 384, 128, 128);
    convert_w<<<(128 * 256 + 255) / 256, 256>>>(wo1, wh + OFF_WO1, wl + OFF_WO1, 128, 256, 256);
    convert_w<<<(128 * 128 + 255) / 256, 256>>>(wo2, wh + OFF_WO2, wl + OFF_WO2, 128, 128, 128);

    k0_kernel<<<NTILES, THREADS, SMEM_BYTES>>>(
        x, cl, b_in, b1, b2, wh + OFF_W1, wl + OFF_W1, fA, pP);

    mid_kernel<<<NTILES, THREADS, SMEM_BYTES>>>(
        fA, fB, cl, cl + BN, pP, pP + PSTRIDE, 32,
        wh + OFF_W3, wl + OFF_W3, b3,
        wh + OFF_W1 + 64 * 256, wl + OFF_W1 + 64 * 256, b1 + 64,
        wh + OFF_W2 + 128 * 64, wl + OFF_W2 + 128 * 64, b2 + 128);

    mid_kernel<<<NTILES, THREADS, SMEM_BYTES>>>(
        fB, fA, cl + BN, cl + 2 * BN, pP + PSTRIDE, pP + 2 * PSTRIDE, 64,
        wh + OFF_W3 + 128 * 128, wl + OFF_W3 + 128 * 128, b3 + 128,
        wh + OFF_W1 + 2 * 64 * 256, wl + OFF_W1 + 2 * 64 * 256, b1 + 2 * 64,
        wh + OFF_W2 + 2 * 128 * 64, wl + OFF_W2 + 2 * 128 * 64, b2 + 2 * 128);

    final_kernel<<<NTILES, THREADS, SMEM_BYTES>>>(
        fA, cl + 2 * BN, pP + 2 * PSTRIDE,
        wh + OFF_W3 + 2 * 128 * 128, wl + OFF_W3 + 2 * 128 * 128, b3 + 2 * 128,
        bo1, bo2, out);
}

// round 3
// speedup vs baseline: 2.1708x; 1.2935x over previous
#include <cuda_runtime.h>
#include <cuda_bf16.h>

#define BATCH   8
#define NPTS    16384
#define BN      (BATCH * NPTS)     // 131072 points
#define TILE    64                 // points per CTA
#define NTILES  (BN / TILE)        // 2048
#define THREADS 512                // 16 warps

// ---------------- smem layout (units: bf16 elements) ----------------
#define LD_CAT 264
#define LD_IO  136
#define LD_MID 72
#define CAT_H  0
#define CAT_L  (CAT_H + 64*LD_CAT)          // 16896
#define IO_H   (CAT_L + 64*LD_CAT)          // 33792
#define IO_L   (IO_H  + 64*LD_IO)           // 42496
#define MID_H  (IO_L  + 64*LD_IO)           // 51200
#define MID_L  (MID_H + 64*LD_MID)          // 55808
#define WS_H   (MID_L + 64*LD_MID)          // 60416 (weight chunk hi, max 128*136=17408)
#define WS_L   (WS_H + 17408)               // 77824
#define SM_BF16 (WS_L + 17408)              // 95232
#define SMEM_BYTES (SM_BF16*2 + 512)        // 190976 B

// ---------------- global scratch ----------------
__device__ unsigned g_featA[BN * 128];
__device__ unsigned g_featB[BN * 128];
__device__ float    g_pool[3 * BATCH * 64 * 128];
__device__ __nv_bfloat16 g_wh[180224];
__device__ __nv_bfloat16 g_wl[180224];

#define OFF_WIN 0        // 256 x 32
#define OFF_W1  8192     // 192 x 256
#define OFF_W2  57344    // 384 x 64
#define OFF_W3  81920    // 384 x 128
#define OFF_WO1 131072   // 128 x 256
#define OFF_WO2 163840   // 128 x 128

__global__ void init_kernel(float* __restrict__ out) {
    int i = blockIdx.x * blockDim.x + threadIdx.x;
    if (i < 3 * BATCH * 64 * 128) g_pool[i] = 0.0f;
    if (i < BATCH * 128) out[i] = 0.0f;
}

__global__ void convert_all(const float* __restrict__ w_in, const float* __restrict__ w1,
                            const float* __restrict__ w2, const float* __restrict__ w3,
                            const float* __restrict__ wo1, const float* __restrict__ wo2) {
    int i = blockIdx.x * blockDim.x + threadIdx.x;
    if (i >= 180224) return;
    const float* src; int base, cin, kpad;
    if (i < 8192)        { src = w_in; base = 0;      cin = 28;  kpad = 32;  }
    else if (i < 57344)  { src = w1;   base = 8192;   cin = 256; kpad = 256; }
    else if (i < 81920)  { src = w2;   base = 57344;  cin = 64;  kpad = 64;  }
    else if (i < 131072) { src = w3;   base = 81920;  cin = 128; kpad = 128; }
    else if (i < 163840) { src = wo1;  base = 131072; cin = 256; kpad = 256; }
    else                 { src = wo2;  base = 163840; cin = 128; kpad = 128; }
    int j = i - base, r = j / kpad, k = j - r * kpad;
    float v = (k < cin) ? src[r * cin + k] : 0.0f;
    __nv_bfloat16 h = __float2bfloat16(v);
    g_wh[i] = h;
    g_wl[i] = __float2bfloat16(v - __bfloat162float(h));
}

// ---------------- helpers ----------------
__device__ __forceinline__ void mma_bf16(float c[4], const unsigned a[4],
                                         unsigned b0, unsigned b1) {
    asm volatile(
        "mma.sync.aligned.m16n8k16.row.col.f32.bf16.bf16.f32 "
        "{%0,%1,%2,%3}, {%4,%5,%6,%7}, {%8,%9}, {%0,%1,%2,%3};"
        : "+f"(c[0]), "+f"(c[1]), "+f"(c[2]), "+f"(c[3])
        : "r"(a[0]), "r"(a[1]), "r"(a[2]), "r"(a[3]), "r"(b0), "r"(b1));
}
__device__ __forceinline__ unsigned lds_u32(const __nv_bfloat16* p) {
    return *reinterpret_cast<const unsigned*>(p);
}
__device__ __forceinline__ unsigned pack2(__nv_bfloat16 x, __nv_bfloat16 y) {
    return ((unsigned)__bfloat16_as_ushort(y) << 16) | (unsigned)__bfloat16_as_ushort(x);
}
__device__ __forceinline__ unsigned sptr(const void* p) {
    return (unsigned)__cvta_generic_to_shared(p);
}
#define CP16(d, s) asm volatile("cp.async.cg.shared.global [%0], [%1], 16;" :: "r"(d), "l"(s))

// ---------------- fused GEMM + bias + ReLU + bf16-split writeback ----------------
// 16 warps: 4 m-groups (16 rows) x 4 n-groups. Split-bf16: Ah*Wh + Al*Wh + Ah*Wl.
template<int NT, int KW>   // COUT = NT*32
__device__ void gemm_relu(__nv_bfloat16* sm,
                          int aH, int aL, int ldA,
                          const __nv_bfloat16* __restrict__ gWh,
                          const __nv_bfloat16* __restrict__ gWl,
                          const float* __restrict__ gBias,
                          int cH, int cL, int ldC)
{
    constexpr int COUT = NT * 32;
    constexpr int KC   = (KW <= 128) ? KW : 128;
    constexpr int LDW  = KC + 8;
    constexpr int NCH  = KW / KC;
    constexpr int NV   = KC / 8;          // 16B vectors per row
    const int tid  = threadIdx.x;
    const int lane = tid & 31;
    const int w    = tid >> 5;
    const int g    = lane >> 2;
    const int t    = lane & 3;
    const int mg   = w & 3;
    const int ng   = w >> 2;

    __nv_bfloat16* sWh = sm + WS_H;
    __nv_bfloat16* sWl = sm + WS_L;

    float acc[NT][4];
#pragma unroll
    for (int nt = 0; nt < NT; nt++)
#pragma unroll
        for (int i = 0; i < 4; i++) acc[nt][i] = 0.0f;

    const __nv_bfloat16* sAh = sm + aH + (mg * 16 + g) * ldA + 2 * t;
    const __nv_bfloat16* sAl = sm + aL + (mg * 16 + g) * ldA + 2 * t;

#pragma unroll
    for (int ch = 0; ch < NCH; ch++) {
        const int kc0 = ch * KC;
        __syncthreads();   // prior users of sW done / prior stage output visible
        for (int idx = tid; idx < COUT * NV; idx += THREADS) {
            int row = idx / NV, v = (idx - row * NV) * 8;
            CP16(sptr(sWh + row * LDW + v), gWh + row * KW + kc0 + v);
            CP16(sptr(sWl + row * LDW + v), gWl + row * KW + kc0 + v);
        }
        asm volatile("cp.async.commit_group;");
        asm volatile("cp.async.wait_group 0;" ::: "memory");
        __syncthreads();

#pragma unroll
        for (int ks = 0; ks < KC; ks += 16) {
            unsigned ah[4], al[4];
            const __nv_bfloat16* ph = sAh + kc0 + ks;
            const __nv_bfloat16* pl = sAl + kc0 + ks;
            ah[0] = lds_u32(ph);           ah[1] = lds_u32(ph + 8 * ldA);
            ah[2] = lds_u32(ph + 8);       ah[3] = lds_u32(ph + 8 * ldA + 8);
            al[0] = lds_u32(pl);           al[1] = lds_u32(pl + 8 * ldA);
            al[2] = lds_u32(pl + 8);       al[3] = lds_u32(pl + 8 * ldA + 8);
#pragma unroll
            for (int nt = 0; nt < NT; nt++) {
                const __nv_bfloat16* pwh = sWh + (ng * (NT * 8) + nt * 8 + g) * LDW + ks + 2 * t;
                const __nv_bfloat16* pwl = sWl + (ng * (NT * 8) + nt * 8 + g) * LDW + ks + 2 * t;
                unsigned bh0 = lds_u32(pwh), bh1 = lds_u32(pwh + 8);
                unsigned bl0 = lds_u32(pwl), bl1 = lds_u32(pwl + 8);
                mma_bf16(acc[nt], ah, bh0, bh1);
                mma_bf16(acc[nt], al, bh0, bh1);
                mma_bf16(acc[nt], ah, bl0, bl1);
            }
        }
    }

    // epilogue
    __nv_bfloat16* sCh = sm + cH;
    __nv_bfloat16* sCl = sm + cL;
#pragma unroll
    for (int nt = 0; nt < NT; nt++) {
        int n0 = ng * (NT * 8) + nt * 8 + 2 * t;
        float bb0 = gBias[n0], bb1 = gBias[n0 + 1];
        int r = mg * 16 + g;
        float v0 = fmaxf(acc[nt][0] + bb0, 0.0f);
        float v1 = fmaxf(acc[nt][1] + bb1, 0.0f);
        float v2 = fmaxf(acc[nt][2] + bb0, 0.0f);
        float v3 = fmaxf(acc[nt][3] + bb1, 0.0f);
        __nv_bfloat16 h0 = __float2bfloat16(v0), h1 = __float2bfloat16(v1);
        __nv_bfloat16 h2 = __float2bfloat16(v2), h3 = __float2bfloat16(v3);
        __nv_bfloat16 l0 = __float2bfloat16(v0 - __bfloat162float(h0));
        __nv_bfloat16 l1 = __float2bfloat16(v1 - __bfloat162float(h1));
        __nv_bfloat16 l2 = __float2bfloat16(v2 - __bfloat162float(h2));
        __nv_bfloat16 l3 = __float2bfloat16(v3 - __bfloat162float(h3));
        *(unsigned*)(sCh + r * ldC + n0)       = pack2(h0, h1);
        *(unsigned*)(sCh + (r + 8) * ldC + n0) = pack2(h2, h3);
        *(unsigned*)(sCl + r * ldC + n0)       = pack2(l0, l1);
        *(unsigned*)(sCl + (r + 8) * ldC + n0) = pack2(l2, l3);
    }
}

// ---------------- feature store + segment-max pool ----------------
__device__ void store_and_pool(__nv_bfloat16* sm, const int* s_cl, int nc, int b,
                               unsigned* __restrict__ gfeat, float* __restrict__ gpool,
                               int P0)
{
    const int tid = threadIdx.x;
    for (int i = tid; i < TILE * 128; i += THREADS) {
        int p = i >> 7, c = i & 127;
        unsigned h = (unsigned)__bfloat16_as_ushort(sm[IO_H + p * LD_IO + c]);
        unsigned l = (unsigned)__bfloat16_as_ushort(sm[IO_L + p * LD_IO + c]);
        gfeat[(size_t)(P0 + p) * 128 + c] = h | (l << 16);
    }
    float* spool = (float*)sm;   // overlays CAT_H plane (free now)
    for (int i = tid; i < nc * 128; i += THREADS) spool[i] = 0.0f;
    __syncthreads();
    for (int i = tid; i < TILE * 128; i += THREADS) {
        int p = i >> 7, c = i & 127;
        float v = __bfloat162float(sm[IO_H + p * LD_IO + c]) +
                  __bfloat162float(sm[IO_L + p * LD_IO + c]);
        atomicMax((int*)&spool[s_cl[p] * 128 + c], __float_as_int(v));
    }
    __syncthreads();
    for (int i = tid; i < nc * 128; i += THREADS) {
        float v = spool[i];
        if (v > 0.0f)
            atomicMax((int*)&gpool[b * (64 * 128) + i], __float_as_int(v));
    }
}

// ---------------- K0 ----------------
__global__ void __launch_bounds__(THREADS)
k0_kernel(const float* __restrict__ x, const int* __restrict__ clusters,
          const float* __restrict__ b_in, const float* __restrict__ b1,
          const float* __restrict__ b2,
          unsigned* __restrict__ gfeat, float* __restrict__ gpool)
{
    extern __shared__ __nv_bfloat16 sm[];
    int* s_cl = (int*)(sm + SM_BF16);
    const int tid = threadIdx.x;
    const int P0  = blockIdx.x * TILE;
    const int b   = P0 / NPTS;

    for (int i = tid; i < TILE * 32; i += THREADS) {
        int p = i >> 5, k = i & 31;
        float v = (k < 28) ? x[(size_t)(P0 + p) * 28 + k] : 0.0f;
        __nv_bfloat16 h = __float2bfloat16(v);
        sm[MID_H + p * LD_MID + k] = h;
        sm[MID_L + p * LD_MID + k] = __float2bfloat16(v - __bfloat162float(h));
    }
    if (tid < TILE) s_cl[tid] = clusters[P0 + tid];

    gemm_relu<8, 32>(sm, MID_H, MID_L, LD_MID, g_wh + OFF_WIN, g_wl + OFF_WIN, b_in, CAT_H, CAT_L, LD_CAT);
    gemm_relu<2, 256>(sm, CAT_H, CAT_L, LD_CAT, g_wh + OFF_W1, g_wl + OFF_W1, b1, MID_H, MID_L, LD_MID);
    gemm_relu<4, 64>(sm, MID_H, MID_L, LD_MID, g_wh + OFF_W2, g_wl + OFF_W2, b2, IO_H, IO_L, LD_IO);
    __syncthreads();

    store_and_pool(sm, s_cl, 16, b, gfeat, gpool, P0);
}

// ---------------- mid blocks ----------------
__global__ void __launch_bounds__(THREADS)
mid_kernel(const unsigned* __restrict__ fin, unsigned* __restrict__ fout,
           const int* __restrict__ cl_in, const int* __restrict__ cl_out,
           const float* __restrict__ gpool_in, float* __restrict__ gpool_out, int nc_out,
           const __nv_bfloat16* __restrict__ wh3, const __nv_bfloat16* __restrict__ wl3,
           const float* __restrict__ b3,
           const __nv_bfloat16* __restrict__ wh1, const __nv_bfloat16* __restrict__ wl1,
           const float* __restrict__ b1,
           const __nv_bfloat16* __restrict__ wh2, const __nv_bfloat16* __restrict__ wl2,
           const float* __restrict__ b2)
{
    extern __shared__ __nv_bfloat16 sm[];
    int* s_cl = (int*)(sm + SM_BF16);
    const int tid = threadIdx.x;
    const int P0  = blockIdx.x * TILE;
    const int b   = P0 / NPTS;

    for (int i = tid; i < TILE * 128; i += THREADS) {
        int p = i >> 7, c = i & 127;
        unsigned u = fin[(size_t)(P0 + p) * 128 + c];
        sm[IO_H + p * LD_IO + c] = __ushort_as_bfloat16((unsigned short)(u & 0xffff));
        sm[IO_L + p * LD_IO + c] = __ushort_as_bfloat16((unsigned short)(u >> 16));
    }
    if (tid < TILE) s_cl[tid] = cl_in[P0 + tid];
    else if (tid < 2 * TILE) s_cl[tid] = cl_out[P0 + tid - TILE];
    __syncthreads();

    for (int i = tid; i < TILE * 128; i += THREADS) {
        int p = i >> 7, c = i & 127;
        float v = gpool_in[(b * 64 + s_cl[p]) * 128 + c];
        __nv_bfloat16 h = __float2bfloat16(v);
        sm[CAT_H + p * LD_CAT + 128 + c] = h;
        sm[CAT_L + p * LD_CAT + 128 + c] = __float2bfloat16(v - __bfloat162float(h));
    }

    gemm_relu<4, 128>(sm, IO_H, IO_L, LD_IO, wh3, wl3, b3, CAT_H, CAT_L, LD_CAT);
    gemm_relu<2, 256>(sm, CAT_H, CAT_L, LD_CAT, wh1, wl1, b1, MID_H, MID_L, LD_MID);
    gemm_relu<4, 64>(sm, MID_H, MID_L, LD_MID, wh2, wl2, b2, IO_H, IO_L, LD_IO);
    __syncthreads();

    store_and_pool(sm, s_cl + TILE, nc_out, b, fout, gpool_out, P0);
}

// ---------------- final ----------------
__global__ void __launch_bounds__(THREADS)
final_kernel(const unsigned* __restrict__ fin, const int* __restrict__ cl_in,
             const float* __restrict__ gpool_in,
             const __nv_bfloat16* __restrict__ wh3, const __nv_bfloat16* __restrict__ wl3,
             const float* __restrict__ b3,
             const float* __restrict__ bo1, const float* __restrict__ bo2,
             float* __restrict__ out)
{
    extern __shared__ __nv_bfloat16 sm[];
    int* s_cl = (int*)(sm + SM_BF16);
    const int tid = threadIdx.x;
    const int P0  = blockIdx.x * TILE;
    const int b   = P0 / NPTS;

    for (int i = tid; i < TILE * 128; i += THREADS) {
        int p = i >> 7, c = i & 127;
        unsigned u = fin[(size_t)(P0 + p) * 128 + c];
        sm[IO_H + p * LD_IO + c] = __ushort_as_bfloat16((unsigned short)(u & 0xffff));
        sm[IO_L + p * LD_IO + c] = __ushort_as_bfloat16((unsigned short)(u >> 16));
    }
    if (tid < TILE) s_cl[tid] = cl_in[P0 + tid];
    __syncthreads();

    for (int i = tid; i < TILE * 128; i += THREADS) {
        int p = i >> 7, c = i & 127;
        float v = gpool_in[(b * 64 + s_cl[p]) * 128 + c];
        __nv_bfloat16 h = __float2bfloat16(v);
        sm[CAT_H + p * LD_CAT + 128 + c] = h;
        sm[CAT_L + p * LD_CAT + 128 + c] = __float2bfloat16(v - __bfloat162float(h));
    }

    gemm_relu<4, 128>(sm, IO_H, IO_L, LD_IO, wh3, wl3, b3, CAT_H, CAT_L, LD_CAT);
    gemm_relu<4, 256>(sm, CAT_H, CAT_L, LD_CAT, g_wh + OFF_WO1, g_wl + OFF_WO1, bo1, IO_H, IO_L, LD_IO);
    gemm_relu<4, 128>(sm, IO_H, IO_L, LD_IO, g_wh + OFF_WO2, g_wl + OFF_WO2, bo2, CAT_H, CAT_L, LD_CAT);
    __syncthreads();

    if (tid < 128) {
        float m = 0.0f;
        for (int p = 0; p < TILE; p++)
            m = fmaxf(m, __bfloat162float(sm[CAT_H + p * LD_CAT + tid]) +
                         __bfloat162float(sm[CAT_L + p * LD_CAT + tid]));
        atomicMax((int*)&out[b * 128 + tid], __float_as_int(m));
    }
}

extern "C" void kernel_launch(void* const* d_in, const int* in_sizes, int n_in,
                              void* d_out, int out_size)
{
    const float* x    = (const float*)d_in[0];
    const int*   cl   = (const int*)  d_in[1];
    const float* w_in = (const float*)d_in[2];
    const float* b_in = (const float*)d_in[3];
    const float* w1   = (const float*)d_in[4];
    const float* b1   = (const float*)d_in[5];
    const float* w2   = (const float*)d_in[6];
    const float* b2   = (const float*)d_in[7];
    const float* w3   = (const float*)d_in[8];
    const float* b3   = (const float*)d_in[9];
    const float* wo1  = (const float*)d_in[10];
    const float* bo1  = (const float*)d_in[11];
    const float* wo2  = (const float*)d_in[12];
    const float* bo2  = (const float*)d_in[13];
    float* out = (float*)d_out;

    void *pa_, *pb_, *pp_, *ph_, *pl_;
    cudaGetSymbolAddress(&pa_, g_featA);
    cudaGetSymbolAddress(&pb_, g_featB);
    cudaGetSymbolAddress(&pp_, g_pool);
    cudaGetSymbolAddress(&ph_, g_wh);
    cudaGetSymbolAddress(&pl_, g_wl);
    unsigned* fA = (unsigned*)pa_;
    unsigned* fB = (unsigned*)pb_;
    float* pP = (float*)pp_;
    __nv_bfloat16* wh = (__nv_bfloat16*)ph_;
    __nv_bfloat16* wl = (__nv_bfloat16*)pl_;

    cudaFuncSetAttribute(k0_kernel,    cudaFuncAttributeMaxDynamicSharedMemorySize, SMEM_BYTES);
    cudaFuncSetAttribute(mid_kernel,   cudaFuncAttributeMaxDynamicSharedMemorySize, SMEM_BYTES);
    cudaFuncSetAttribute(final_kernel, cudaFuncAttributeMaxDynamicSharedMemorySize, SMEM_BYTES);

    const int PSTRIDE = BATCH * 64 * 128;

    init_kernel<<<(3 * PSTRIDE + 255) / 256, 256>>>(out);
    convert_all<<<(180224 + 255) / 256, 256>>>(w_in, w1, w2, w3, wo1, wo2);

    k0_kernel<<<NTILES, THREADS, SMEM_BYTES>>>(x, cl, b_in, b1, b2, fA, pP);

    mid_kernel<<<NTILES, THREADS, SMEM_BYTES>>>(
        fA, fB, cl, cl + BN, pP, pP + PSTRIDE, 32,
        wh + OFF_W3, wl + OFF_W3, b3,
        wh + OFF_W1 + 64 * 256, wl + OFF_W1 + 64 * 256, b1 + 64,
        wh + OFF_W2 + 128 * 64, wl + OFF_W2 + 128 * 64, b2 + 128);

    mid_kernel<<<NTILES, THREADS, SMEM_BYTES>>>(
        fB, fA, cl + BN, cl + 2 * BN, pP + PSTRIDE, pP + 2 * PSTRIDE, 64,
        wh + OFF_W3 + 128 * 128, wl + OFF_W3 + 128 * 128, b3 + 128,
        wh + OFF_W1 + 2 * 64 * 256, wl + OFF_W1 + 2 * 64 * 256, b1 + 2 * 64,
        wh + OFF_W2 + 2 * 128 * 64, wl + OFF_W2 + 2 * 128 * 64, b2 + 2 * 128);

    final_kernel<<<NTILES, THREADS, SMEM_BYTES>>>(
        fA, cl + 2 * BN, pP + 2 * PSTRIDE,
        wh + OFF_W3 + 2 * 128 * 128, wl + OFF_W3 + 2 * 128 * 128, b3 + 2 * 128,
        bo1, bo2, out);
}

// round 4
// speedup vs baseline: 2.2512x; 1.0370x over previous
#include <cuda_runtime.h>
#include <cuda_bf16.h>

#define BATCH   8
#define NPTS    16384
#define BN      (BATCH * NPTS)
#define TILE    64
#define NTILES  (BN / TILE)        // 2048
#define THREADS 512                // 16 warps

// ---------------- smem layout (bf16 units) ----------------
#define LD_CAT 264
#define LD_IO  136
#define LD_MID 72
#define CAT_H  0
#define CAT_L  (CAT_H + 64*LD_CAT)
#define IO_H   (CAT_L + 64*LD_CAT)
#define IO_L   (IO_H  + 64*LD_IO)
#define MID_H  (IO_L  + 64*LD_IO)
#define MID_L  (MID_H + 64*LD_MID)
#define WS_BASE (MID_L + 64*LD_MID)         // 60416
#define WSEG   10240                        // one weight buffer plane (max 256x40 / 128x72)
#define SM_BF16 (WS_BASE + 4*WSEG)          // 101376
#define SMEM_BYTES (SM_BF16*2 + 512)        // 203264 B

// ---------------- global scratch ----------------
__device__ unsigned g_featA[BN * 128];
__device__ unsigned g_featB[BN * 128];
__device__ float    g_pool[3 * BATCH * 64 * 128];
__device__ __nv_bfloat16 g_wh[180224];
__device__ __nv_bfloat16 g_wl[180224];

#define OFF_WIN 0        // 256 x 32
#define OFF_W1  8192     // 192 x 256
#define OFF_W2  57344    // 384 x 64
#define OFF_W3  81920    // 384 x 128
#define OFF_WO1 131072   // 128 x 256
#define OFF_WO2 163840   // 128 x 128

__global__ void init_kernel(float* __restrict__ out) {
    int i = blockIdx.x * blockDim.x + threadIdx.x;
    if (i < 3 * BATCH * 64 * 128) g_pool[i] = 0.0f;
    if (i < BATCH * 128) out[i] = 0.0f;
}

__global__ void convert_all(const float* __restrict__ w_in, const float* __restrict__ w1,
                            const float* __restrict__ w2, const float* __restrict__ w3,
                            const float* __restrict__ wo1, const float* __restrict__ wo2) {
    int i = blockIdx.x * blockDim.x + threadIdx.x;
    if (i >= 180224) return;
    const float* src; int base, cin, kpad;
    if (i < 8192)        { src = w_in; base = 0;      cin = 28;  kpad = 32;  }
    else if (i < 57344)  { src = w1;   base = 8192;   cin = 256; kpad = 256; }
    else if (i < 81920)  { src = w2;   base = 57344;  cin = 64;  kpad = 64;  }
    else if (i < 131072) { src = w3;   base = 81920;  cin = 128; kpad = 128; }
    else if (i < 163840) { src = wo1;  base = 131072; cin = 256; kpad = 256; }
    else                 { src = wo2;  base = 163840; cin = 128; kpad = 128; }
    int j = i - base, r = j / kpad, k = j - r * kpad;
    float v = (k < cin) ? src[r * cin + k] : 0.0f;
    __nv_bfloat16 h = __float2bfloat16(v);
    g_wh[i] = h;
    g_wl[i] = __float2bfloat16(v - __bfloat162float(h));
}

// ---------------- helpers ----------------
__device__ __forceinline__ void mma_bf16(float c[4], const unsigned a[4],
                                         unsigned b0, unsigned b1) {
    asm volatile(
        "mma.sync.aligned.m16n8k16.row.col.f32.bf16.bf16.f32 "
        "{%0,%1,%2,%3}, {%4,%5,%6,%7}, {%8,%9}, {%0,%1,%2,%3};"
        : "+f"(c[0]), "+f"(c[1]), "+f"(c[2]), "+f"(c[3])
        : "r"(a[0]), "r"(a[1]), "r"(a[2]), "r"(a[3]), "r"(b0), "r"(b1));
}
__device__ __forceinline__ unsigned sptr(const void* p) {
    return (unsigned)__cvta_generic_to_shared(p);
}
__device__ __forceinline__ void ldsm4(unsigned r[4], const void* p) {
    asm volatile("ldmatrix.sync.aligned.m8n8.x4.shared.b16 {%0,%1,%2,%3}, [%4];"
                 : "=r"(r[0]), "=r"(r[1]), "=r"(r[2]), "=r"(r[3]) : "r"(sptr(p)));
}
__device__ __forceinline__ unsigned pack2(__nv_bfloat16 x, __nv_bfloat16 y) {
    return ((unsigned)__bfloat16_as_ushort(y) << 16) | (unsigned)__bfloat16_as_ushort(x);
}
#define CP16(d, s) asm volatile("cp.async.cg.shared.global [%0], [%1], 16;" :: "r"(d), "l"(s))

// ---------------- fused GEMM + bias + ReLU + split-bf16 writeback ----------------
// 16 warps: 4 m-groups x 4 n-groups. Double-buffered KC=64 weight staging + ldmatrix.
template<int NT, int KW>   // COUT = NT*32
__device__ void gemm_relu(__nv_bfloat16* sm,
                          int aH, int aL, int ldA,
                          const __nv_bfloat16* __restrict__ gWh,
                          const __nv_bfloat16* __restrict__ gWl,
                          const float* __restrict__ gBias,
                          int cH, int cL, int ldC)
{
    constexpr int COUT = NT * 32;
    constexpr int KC   = (KW < 64) ? KW : 64;
    constexpr int NCH  = KW / KC;
    constexpr int LDW  = KC + 8;
    constexpr int NV   = KC / 8;
    const int tid  = threadIdx.x;
    const int lane = tid & 31;
    const int w    = tid >> 5;
    const int g    = lane >> 2;
    const int t    = lane & 3;
    const int mg   = w & 3;
    const int ng   = w >> 2;

    float acc[NT][4];
#pragma unroll
    for (int nt = 0; nt < NT; nt++)
#pragma unroll
        for (int i = 0; i < 4; i++) acc[nt][i] = 0.0f;

    __syncthreads();   // activations from prior stage visible; WS buffers free

    // stage chunk ch into buffer buf (both planes, one commit group)
    auto issue = [&](int ch, int buf) {
        __nv_bfloat16* dh = sm + WS_BASE + (buf * 2 + 0) * WSEG;
        __nv_bfloat16* dl = sm + WS_BASE + (buf * 2 + 1) * WSEG;
        const __nv_bfloat16* sh = gWh + ch * KC;
        const __nv_bfloat16* sl = gWl + ch * KC;
        for (int idx = tid; idx < COUT * NV; idx += THREADS) {
            int row = idx / NV, v = (idx - row * NV) * 8;
            CP16(sptr(dh + row * LDW + v), sh + row * KW + v);
            CP16(sptr(dl + row * LDW + v), sl + row * KW + v);
        }
        asm volatile("cp.async.commit_group;");
    };

    issue(0, 0);
    if (NCH > 1) issue(1, 1);

    // ldmatrix per-lane bases
    const int arow = mg * 16 + (lane & 15);
    const int ac8  = ((lane >> 4) & 1) * 8;
    const __nv_bfloat16* pAh = sm + aH + arow * ldA + ac8;
    const __nv_bfloat16* pAl = sm + aL + arow * ldA + ac8;
    const int brow = (lane & 7) + ((lane >> 4) & 1) * 8;
    const int bc8  = ((lane >> 3) & 1) * 8;

#pragma unroll
    for (int ch = 0; ch < NCH; ch++) {
        if (ch < NCH - 1) asm volatile("cp.async.wait_group 1;" ::: "memory");
        else              asm volatile("cp.async.wait_group 0;" ::: "memory");
        __syncthreads();
        const __nv_bfloat16* sWh = sm + WS_BASE + ((ch & 1) * 2 + 0) * WSEG;
        const __nv_bfloat16* sWl = sm + WS_BASE + ((ch & 1) * 2 + 1) * WSEG;
#pragma unroll
        for (int ks = 0; ks < KC; ks += 16) {
            unsigned ah[4], al[4];
            ldsm4(ah, pAh + ch * KC + ks);
            ldsm4(al, pAl + ch * KC + ks);
#pragma unroll
            for (int nt = 0; nt < NT; nt += 2) {
                unsigned bh[4], bl[4];
                const __nv_bfloat16* ph = sWh + (ng * (NT * 8) + nt * 8 + brow) * LDW + bc8 + ks;
                const __nv_bfloat16* pl = sWl + (ng * (NT * 8) + nt * 8 + brow) * LDW + bc8 + ks;
                ldsm4(bh, ph);
                ldsm4(bl, pl);
                mma_bf16(acc[nt], ah, bh[0], bh[1]);
                mma_bf16(acc[nt], al, bh[0], bh[1]);
                mma_bf16(acc[nt], ah, bl[0], bl[1]);
                mma_bf16(acc[nt + 1], ah, bh[2], bh[3]);
                mma_bf16(acc[nt + 1], al, bh[2], bh[3]);
                mma_bf16(acc[nt + 1], ah, bl[2], bl[3]);
            }
        }
        if (ch + 2 < NCH) { __syncthreads(); issue(ch + 2, ch & 1); }
    }

    // epilogue: bias + relu + split-bf16 writeback
    __nv_bfloat16* sCh = sm + cH;
    __nv_bfloat16* sCl = sm + cL;
#pragma unroll
    for (int nt = 0; nt < NT; nt++) {
        int n0 = ng * (NT * 8) + nt * 8 + 2 * t;
        float bb0 = gBias[n0], bb1 = gBias[n0 + 1];
        int r = mg * 16 + g;
        float v0 = fmaxf(acc[nt][0] + bb0, 0.0f);
        float v1 = fmaxf(acc[nt][1] + bb1, 0.0f);
        float v2 = fmaxf(acc[nt][2] + bb0, 0.0f);
        float v3 = fmaxf(acc[nt][3] + bb1, 0.0f);
        __nv_bfloat16 h0 = __float2bfloat16(v0), h1 = __float2bfloat16(v1);
        __nv_bfloat16 h2 = __float2bfloat16(v2), h3 = __float2bfloat16(v3);
        __nv_bfloat16 l0 = __float2bfloat16(v0 - __bfloat162float(h0));
        __nv_bfloat16 l1 = __float2bfloat16(v1 - __bfloat162float(h1));
        __nv_bfloat16 l2 = __float2bfloat16(v2 - __bfloat162float(h2));
        __nv_bfloat16 l3 = __float2bfloat16(v3 - __bfloat162float(h3));
        *(unsigned*)(sCh + r * ldC + n0)       = pack2(h0, h1);
        *(unsigned*)(sCh + (r + 8) * ldC + n0) = pack2(h2, h3);
        *(unsigned*)(sCl + r * ldC + n0)       = pack2(l0, l1);
        *(unsigned*)(sCl + (r + 8) * ldC + n0) = pack2(l2, l3);
    }
}

// ---------------- feature store + segment-max pool ----------------
__device__ void store_and_pool(__nv_bfloat16* sm, const int* s_cl, int nc, int b,
                               unsigned* __restrict__ gfeat, float* __restrict__ gpool,
                               int P0)
{
    const int tid = threadIdx.x;
    for (int i = tid; i < TILE * 128; i += THREADS) {
        int p = i >> 7, c = i & 127;
        unsigned h = (unsigned)__bfloat16_as_ushort(sm[IO_H + p * LD_IO + c]);
        unsigned l = (unsigned)__bfloat16_as_ushort(sm[IO_L + p * LD_IO + c]);
        gfeat[(size_t)(P0 + p) * 128 + c] = h | (l << 16);
    }
    float* spool = (float*)sm;   // overlays CAT_H (free now)
    for (int i = tid; i < nc * 128; i += THREADS) spool[i] = 0.0f;
    __syncthreads();
    for (int i = tid; i < TILE * 128; i += THREADS) {
        int p = i >> 7, c = i & 127;
        float v = __bfloat162float(sm[IO_H + p * LD_IO + c]) +
                  __bfloat162float(sm[IO_L + p * LD_IO + c]);
        atomicMax((int*)&spool[s_cl[p] * 128 + c], __float_as_int(v));
    }
    __syncthreads();
    for (int i = tid; i < nc * 128; i += THREADS) {
        float v = spool[i];
        if (v > 0.0f)
            atomicMax((int*)&gpool[b * (64 * 128) + i], __float_as_int(v));
    }
}

// ---------------- K0 ----------------
__global__ void __launch_bounds__(THREADS)
k0_kernel(const float* __restrict__ x, const int* __restrict__ clusters,
          const float* __restrict__ b_in, const float* __restrict__ b1,
          const float* __restrict__ b2,
          unsigned* __restrict__ gfeat, float* __restrict__ gpool)
{
    extern __shared__ __nv_bfloat16 sm[];
    int* s_cl = (int*)(sm + SM_BF16);
    const int tid = threadIdx.x;
    const int P0  = blockIdx.x * TILE;
    const int b   = P0 / NPTS;

    for (int i = tid; i < TILE * 32; i += THREADS) {
        int p = i >> 5, k = i & 31;
        float v = (k < 28) ? x[(size_t)(P0 + p) * 28 + k] : 0.0f;
        __nv_bfloat16 h = __float2bfloat16(v);
        sm[MID_H + p * LD_MID + k] = h;
        sm[MID_L + p * LD_MID + k] = __float2bfloat16(v - __bfloat162float(h));
    }
    if (tid < TILE) s_cl[tid] = clusters[P0 + tid];

    gemm_relu<8, 32>(sm, MID_H, MID_L, LD_MID, g_wh + OFF_WIN, g_wl + OFF_WIN, b_in, CAT_H, CAT_L, LD_CAT);
    gemm_relu<2, 256>(sm, CAT_H, CAT_L, LD_CAT, g_wh + OFF_W1, g_wl + OFF_W1, b1, MID_H, MID_L, LD_MID);
    gemm_relu<4, 64>(sm, MID_H, MID_L, LD_MID, g_wh + OFF_W2, g_wl + OFF_W2, b2, IO_H, IO_L, LD_IO);
    __syncthreads();

    store_and_pool(sm, s_cl, 16, b, gfeat, gpool, P0);
}

// ---------------- mid blocks ----------------
__global__ void __launch_bounds__(THREADS)
mid_kernel(const unsigned* __restrict__ fin, unsigned* __restrict__ fout,
           const int* __restrict__ cl_in, const int* __restrict__ cl_out,
           const float* __restrict__ gpool_in, float* __restrict__ gpool_out, int nc_out,
           const __nv_bfloat16* __restrict__ wh3, const __nv_bfloat16* __restrict__ wl3,
           const float* __restrict__ b3,
           const __nv_bfloat16* __restrict__ wh1, const __nv_bfloat16* __restrict__ wl1,
           const float* __restrict__ b1,
           const __nv_bfloat16* __restrict__ wh2, const __nv_bfloat16* __restrict__ wl2,
           const float* __restrict__ b2)
{
    extern __shared__ __nv_bfloat16 sm[];
    int* s_cl = (int*)(sm + SM_BF16);
    const int tid = threadIdx.x;
    const int P0  = blockIdx.x * TILE;
    const int b   = P0 / NPTS;

    for (int i = tid; i < TILE * 128; i += THREADS) {
        int p = i >> 7, c = i & 127;
        unsigned u = fin[(size_t)(P0 + p) * 128 + c];
        sm[IO_H + p * LD_IO + c] = __ushort_as_bfloat16((unsigned short)(u & 0xffff));
        sm[IO_L + p * LD_IO + c] = __ushort_as_bfloat16((unsigned short)(u >> 16));
    }
    if (tid < TILE) s_cl[tid] = cl_in[P0 + tid];
    else if (tid < 2 * TILE) s_cl[tid] = cl_out[P0 + tid - TILE];
    __syncthreads();

    for (int i = tid; i < TILE * 128; i += THREADS) {
        int p = i >> 7, c = i & 127;
        float v = gpool_in[(b * 64 + s_cl[p]) * 128 + c];
        __nv_bfloat16 h = __float2bfloat16(v);
        sm[CAT_H + p * LD_CAT + 128 + c] = h;
        sm[CAT_L + p * LD_CAT + 128 + c] = __float2bfloat16(v - __bfloat162float(h));
    }

    gemm_relu<4, 128>(sm, IO_H, IO_L, LD_IO, wh3, wl3, b3, CAT_H, CAT_L, LD_CAT);
    gemm_relu<2, 256>(sm, CAT_H, CAT_L, LD_CAT, wh1, wl1, b1, MID_H, MID_L, LD_MID);
    gemm_relu<4, 64>(sm, MID_H, MID_L, LD_MID, wh2, wl2, b2, IO_H, IO_L, LD_IO);
    __syncthreads();

    store_and_pool(sm, s_cl + TILE, nc_out, b, fout, gpool_out, P0);
}

// ---------------- final ----------------
__global__ void __launch_bounds__(THREADS)
final_kernel(const unsigned* __restrict__ fin, const int* __restrict__ cl_in,
             const float* __restrict__ gpool_in,
             const __nv_bfloat16* __restrict__ wh3, const __nv_bfloat16* __restrict__ wl3,
             const float* __restrict__ b3,
             const float* __restrict__ bo1, const float* __restrict__ bo2,
             float* __restrict__ out)
{
    extern __shared__ __nv_bfloat16 sm[];
    int* s_cl = (int*)(sm + SM_BF16);
    const int tid = threadIdx.x;
    const int P0  = blockIdx.x * TILE;
    const int b   = P0 / NPTS;

    for (int i = tid; i < TILE * 128; i += THREADS) {
        int p = i >> 7, c = i & 127;
        unsigned u = fin[(size_t)(P0 + p) * 128 + c];
        sm[IO_H + p * LD_IO + c] = __ushort_as_bfloat16((unsigned short)(u & 0xffff));
        sm[IO_L + p * LD_IO + c] = __ushort_as_bfloat16((unsigned short)(u >> 16));
    }
    if (tid < TILE) s_cl[tid] = cl_in[P0 + tid];
    __syncthreads();

    for (int i = tid; i < TILE * 128; i += THREADS) {
        int p = i >> 7, c = i & 127;
        float v = gpool_in[(b * 64 + s_cl[p]) * 128 + c];
        __nv_bfloat16 h = __float2bfloat16(v);
        sm[CAT_H + p * LD_CAT + 128 + c] = h;
        sm[CAT_L + p * LD_CAT + 128 + c] = __float2bfloat16(v - __bfloat162float(h));
    }

    gemm_relu<4, 128>(sm, IO_H, IO_L, LD_IO, wh3, wl3, b3, CAT_H, CAT_L, LD_CAT);
    gemm_relu<4, 256>(sm, CAT_H, CAT_L, LD_CAT, g_wh + OFF_WO1, g_wl + OFF_WO1, bo1, IO_H, IO_L, LD_IO);
    gemm_relu<4, 128>(sm, IO_H, IO_L, LD_IO, g_wh + OFF_WO2, g_wl + OFF_WO2, bo2, CAT_H, CAT_L, LD_CAT);
    __syncthreads();

    if (tid < 128) {
        float m = 0.0f;
        for (int p = 0; p < TILE; p++)
            m = fmaxf(m, __bfloat162float(sm[CAT_H + p * LD_CAT + tid]) +
                         __bfloat162float(sm[CAT_L + p * LD_CAT + tid]));
        atomicMax((int*)&out[b * 128 + tid], __float_as_int(m));
    }
}

extern "C" void kernel_launch(void* const* d_in, const int* in_sizes, int n_in,
                              void* d_out, int out_size)
{
    const float* x    = (const float*)d_in[0];
    const int*   cl   = (const int*)  d_in[1];
    const float* w_in = (const float*)d_in[2];
    const float* b_in = (const float*)d_in[3];
    const float* w1   = (const float*)d_in[4];
    const float* b1   = (const float*)d_in[5];
    const float* w2   = (const float*)d_in[6];
    const float* b2   = (const float*)d_in[7];
    const float* w3   = (const float*)d_in[8];
    const float* b3   = (const float*)d_in[9];
    const float* wo1  = (const float*)d_in[10];
    const float* bo1  = (const float*)d_in[11];
    const float* wo2  = (const float*)d_in[12];
    const float* bo2  = (const float*)d_in[13];
    float* out = (float*)d_out;

    void *pa_, *pb_, *pp_, *ph_, *pl_;
    cudaGetSymbolAddress(&pa_, g_featA);
    cudaGetSymbolAddress(&pb_, g_featB);
    cudaGetSymbolAddress(&pp_, g_pool);
    cudaGetSymbolAddress(&ph_, g_wh);
    cudaGetSymbolAddress(&pl_, g_wl);
    unsigned* fA = (unsigned*)pa_;
    unsigned* fB = (unsigned*)pb_;
    float* pP = (float*)pp_;
    __nv_bfloat16* wh = (__nv_bfloat16*)ph_;
    __nv_bfloat16* wl = (__nv_bfloat16*)pl_;

    cudaFuncSetAttribute(k0_kernel,    cudaFuncAttributeMaxDynamicSharedMemorySize, SMEM_BYTES);
    cudaFuncSetAttribute(mid_kernel,   cudaFuncAttributeMaxDynamicSharedMemorySize, SMEM_BYTES);
    cudaFuncSetAttribute(final_kernel, cudaFuncAttributeMaxDynamicSharedMemorySize, SMEM_BYTES);

    const int PSTRIDE = BATCH * 64 * 128;

    init_kernel<<<(3 * PSTRIDE + 255) / 256, 256>>>(out);
    convert_all<<<(180224 + 255) / 256, 256>>>(w_in, w1, w2, w3, wo1, wo2);

    k0_kernel<<<NTILES, THREADS, SMEM_BYTES>>>(x, cl, b_in, b1, b2, fA, pP);

    mid_kernel<<<NTILES, THREADS, SMEM_BYTES>>>(
        fA, fB, cl, cl + BN, pP, pP + PSTRIDE, 32,
        wh + OFF_W3, wl + OFF_W3, b3,
        wh + OFF_W1 + 64 * 256, wl + OFF_W1 + 64 * 256, b1 + 64,
        wh + OFF_W2 + 128 * 64, wl + OFF_W2 + 128 * 64, b2 + 128);

    mid_kernel<<<NTILES, THREADS, SMEM_BYTES>>>(
        fB, fA, cl + BN, cl + 2 * BN, pP + PSTRIDE, pP + 2 * PSTRIDE, 64,
        wh + OFF_W3 + 128 * 128, wl + OFF_W3 + 128 * 128, b3 + 128,
        wh + OFF_W1 + 2 * 64 * 256, wl + OFF_W1 + 2 * 64 * 256, b1 + 2 * 64,
        wh + OFF_W2 + 2 * 128 * 64, wl + OFF_W2 + 2 * 128 * 64, b2 + 2 * 128);

    final_kernel<<<NTILES, THREADS, SMEM_BYTES>>>(
        fA, cl + 2 * BN, pP + 2 * PSTRIDE,
        wh + OFF_W3 + 2 * 128 * 128, wl + OFF_W3 + 2 * 128 * 128, b3 + 2 * 128,
        bo1, bo2, out);
}

// round 5
// speedup vs baseline: 2.9526x; 1.3116x over previous
#include <cuda_runtime.h>
#include <cuda_bf16.h>

#define BATCH   8
#define NPTS    16384
#define BN      (BATCH * NPTS)
#define TILE    64
#define NTILES  (BN / TILE)        // 2048
#define THREADS 512                // 16 warps

// ---------------- mid/final smem layout (bf16 units) ----------------
#define MF_P_H  0                  // 64x136 input feats
#define MF_P_L  8704
#define MF_Q_H  17408              // 64x136 (f3 / conv2 out)
#define MF_Q_L  26112
#define MF_R_H  34816              // 64x72 (conv1 out)
#define MF_R_L  39424
#define MF_WS_H 44032              // 128x40 weight chunk (KC=32)
#define MF_WS_L 49152
#define MF_END  54272
#define SMEM_MF (MF_END*2 + 512)   // 109056 B  -> 2 CTAs/SM

// ---------------- k0 smem layout ----------------
#define K0_X_H  0                  // 64x40 (input, K=32 padded)
#define K0_X_L  2560
#define K0_C_H  5120               // 64x264 (mlp_in out, 256-wide)
#define K0_C_L  22016
#define K0_M_H  38912              // 64x72
#define K0_M_L  43520
#define K0_IO_H 48128              // 64x136
#define K0_IO_L 56832
#define K0_WS_H 65536              // 256x40
#define K0_WS_L 75776
#define K0_END  86016
#define SMEM_K0 (K0_END*2 + 512)   // 172544 B -> 1 CTA/SM

#define LD_136 136
#define LD_72  72
#define LD_264 264
#define LD_40  40

// ---------------- global scratch ----------------
__device__ unsigned g_featA[BN * 128];
__device__ unsigned g_featB[BN * 128];
__device__ float    g_pool[3 * BATCH * 64 * 128];
__device__ float    g_p2l[8 * 64 * 128];          // pool-linear tables (reused)
__device__ __nv_bfloat16 g_wh[180224];
__device__ __nv_bfloat16 g_wl[180224];

#define OFF_WIN 0        // 256 x 32
#define OFF_W1  8192     // 3 x (64 x 256)
#define OFF_W2  57344    // 3 x (128 x 64)
#define OFF_W3  81920    // 3 x (128 x 128)
#define OFF_WO1 131072   // 128 x 256
#define OFF_WO2 163840   // 128 x 128

__global__ void init_kernel(float* __restrict__ out) {
    int i = blockIdx.x * blockDim.x + threadIdx.x;
    if (i < 3 * BATCH * 64 * 128) g_pool[i] = 0.0f;
    if (i < BATCH * 128) out[i] = 0.0f;
}

__global__ void convert_all(const float* __restrict__ w_in, const float* __restrict__ w1,
                            const float* __restrict__ w2, const float* __restrict__ w3,
                            const float* __restrict__ wo1, const float* __restrict__ wo2) {
    int i = blockIdx.x * blockDim.x + threadIdx.x;
    if (i >= 180224) return;
    const float* src; int base, cin, kpad;
    if (i < 8192)        { src = w_in; base = 0;      cin = 28;  kpad = 32;  }
    else if (i < 57344)  { src = w1;   base = 8192;   cin = 256; kpad = 256; }
    else if (i < 81920)  { src = w2;   base = 57344;  cin = 64;  kpad = 64;  }
    else if (i < 131072) { src = w3;   base = 81920;  cin = 128; kpad = 128; }
    else if (i < 163840) { src = wo1;  base = 131072; cin = 256; kpad = 256; }
    else                 { src = wo2;  base = 163840; cin = 128; kpad = 128; }
    int j = i - base, r = j / kpad, k = j - r * kpad;
    float v = (k < cin) ? src[r * cin + k] : 0.0f;
    __nv_bfloat16 h = __float2bfloat16(v);
    g_wh[i] = h;
    g_wl[i] = __float2bfloat16(v - __bfloat162float(h));
}

// p2l[b][cl][j] = bias[j] + W[j][128..255] . pool[b][cl][:]   (exact fp32)
__global__ void p2l_kernel(const float* __restrict__ w, const float* __restrict__ bias,
                           const float* __restrict__ pool, float* __restrict__ dst,
                           int ncl, int J) {
    int i = blockIdx.x * blockDim.x + threadIdx.x;
    if (i >= 8 * ncl * J) return;
    int j = i % J, cl = (i / J) % ncl, b = i / (J * ncl);
    const float* wr = w + j * 256 + 128;
    const float* pr = pool + b * 8192 + cl * 128;
    float s = bias[j];
#pragma unroll 16
    for (int k = 0; k < 128; k++) s += wr[k] * pr[k];
    dst[i] = s;
}

// ---------------- helpers ----------------
__device__ __forceinline__ void mma_bf16(float c[4], const unsigned a[4],
                                         unsigned b0, unsigned b1) {
    asm volatile(
        "mma.sync.aligned.m16n8k16.row.col.f32.bf16.bf16.f32 "
        "{%0,%1,%2,%3}, {%4,%5,%6,%7}, {%8,%9}, {%0,%1,%2,%3};"
        : "+f"(c[0]), "+f"(c[1]), "+f"(c[2]), "+f"(c[3])
        : "r"(a[0]), "r"(a[1]), "r"(a[2]), "r"(a[3]), "r"(b0), "r"(b1));
}
__device__ __forceinline__ unsigned sptr(const void* p) {
    return (unsigned)__cvta_generic_to_shared(p);
}
__device__ __forceinline__ void ldsm4(unsigned r[4], const void* p) {
    asm volatile("ldmatrix.sync.aligned.m8n8.x4.shared.b16 {%0,%1,%2,%3}, [%4];"
                 : "=r"(r[0]), "=r"(r[1]), "=r"(r[2]), "=r"(r[3]) : "r"(sptr(p)));
}
__device__ __forceinline__ unsigned pack2(__nv_bfloat16 x, __nv_bfloat16 y) {
    return ((unsigned)__bfloat16_as_ushort(y) << 16) | (unsigned)__bfloat16_as_ushort(x);
}
#define CP16(d, s) asm volatile("cp.async.cg.shared.global [%0], [%1], 16;" :: "r"(d), "l"(s))

// ================= GEMM + relu + split-bf16 smem writeback =================
// KC=32 single-buffer staging. acc init = bias (+ optional per-cluster p2l gather).
// 16 warps: 4 m-groups x 4 n-groups.
template<int NT, int KW, int WSTR, int JSTR>
__device__ void gemm2(__nv_bfloat16* sm, int aH, int aL, int ldA,
                      const __nv_bfloat16* __restrict__ gWh,
                      const __nv_bfloat16* __restrict__ gWl,
                      const float* __restrict__ gBias,
                      const float* __restrict__ p2l, const int* __restrict__ s_cl,
                      int cH, int cL, int ldC, int wsH, int wsL)
{
    constexpr int COUT = NT * 32;
    constexpr int KC   = 32;
    constexpr int NCH  = KW / KC;
    constexpr int LDW  = 40;
    constexpr int NV   = 4;
    const int tid  = threadIdx.x;
    const int lane = tid & 31;
    const int w    = tid >> 5;
    const int g    = lane >> 2;
    const int t    = lane & 3;
    const int mg   = w & 3;
    const int ng   = w >> 2;

    float acc[NT][4];
#pragma unroll
    for (int nt = 0; nt < NT; nt++) {
        int n0 = ng * (NT * 8) + nt * 8 + 2 * t;
        float b0 = gBias ? gBias[n0] : 0.0f;
        float b1 = gBias ? gBias[n0 + 1] : 0.0f;
        if (JSTR) {
            int c0 = s_cl[mg * 16 + g], c1 = s_cl[mg * 16 + g + 8];
            acc[nt][0] = b0 + p2l[c0 * JSTR + n0];
            acc[nt][1] = b1 + p2l[c0 * JSTR + n0 + 1];
            acc[nt][2] = b0 + p2l[c1 * JSTR + n0];
            acc[nt][3] = b1 + p2l[c1 * JSTR + n0 + 1];
        } else {
            acc[nt][0] = b0; acc[nt][1] = b1; acc[nt][2] = b0; acc[nt][3] = b1;
        }
    }

    const int arow = mg * 16 + (lane & 15);
    const int ac8  = ((lane >> 4) & 1) * 8;
    const __nv_bfloat16* pAh = sm + aH + arow * ldA + ac8;
    const __nv_bfloat16* pAl = sm + aL + arow * ldA + ac8;
    const int brow = (lane & 7) + ((lane >> 4) & 1) * 8;
    const int bc8  = ((lane >> 3) & 1) * 8;
    __nv_bfloat16* sWh = sm + wsH;
    __nv_bfloat16* sWl = sm + wsL;

#pragma unroll
    for (int ch = 0; ch < NCH; ch++) {
        __syncthreads();   // WS free / (ch0) prior-stage activations visible
        for (int idx = tid; idx < COUT * NV; idx += THREADS) {
            int row = idx >> 2, v = (idx & 3) * 8;
            CP16(sptr(sWh + row * LDW + v), gWh + row * WSTR + ch * KC + v);
            CP16(sptr(sWl + row * LDW + v), gWl + row * WSTR + ch * KC + v);
        }
        asm volatile("cp.async.commit_group;");
        asm volatile("cp.async.wait_group 0;" ::: "memory");
        __syncthreads();
#pragma unroll
        for (int ks = 0; ks < KC; ks += 16) {
            unsigned ah[4], al[4];
            ldsm4(ah, pAh + ch * KC + ks);
            ldsm4(al, pAl + ch * KC + ks);
#pragma unroll
            for (int nt = 0; nt < NT; nt += 2) {
                unsigned bh[4], bl[4];
                const __nv_bfloat16* ph = sWh + (ng * (NT * 8) + nt * 8 + brow) * LDW + bc8 + ks;
                const __nv_bfloat16* pl = sWl + (ng * (NT * 8) + nt * 8 + brow) * LDW + bc8 + ks;
                ldsm4(bh, ph);
                ldsm4(bl, pl);
                mma_bf16(acc[nt], ah, bh[0], bh[1]);
                mma_bf16(acc[nt], al, bh[0], bh[1]);
                mma_bf16(acc[nt], ah, bl[0], bl[1]);
                if (NT > 1) {
                    mma_bf16(acc[nt + 1], ah, bh[2], bh[3]);
                    mma_bf16(acc[nt + 1], al, bh[2], bh[3]);
                    mma_bf16(acc[nt + 1], ah, bl[2], bl[3]);
                }
            }
        }
    }

    __nv_bfloat16* sCh = sm + cH;
    __nv_bfloat16* sCl = sm + cL;
#pragma unroll
    for (int nt = 0; nt < NT; nt++) {
        int n0 = ng * (NT * 8) + nt * 8 + 2 * t;
        int r = mg * 16 + g;
        float v0 = fmaxf(acc[nt][0], 0.0f);
        float v1 = fmaxf(acc[nt][1], 0.0f);
        float v2 = fmaxf(acc[nt][2], 0.0f);
        float v3 = fmaxf(acc[nt][3], 0.0f);
        __nv_bfloat16 h0 = __float2bfloat16(v0), h1 = __float2bfloat16(v1);
        __nv_bfloat16 h2 = __float2bfloat16(v2), h3 = __float2bfloat16(v3);
        __nv_bfloat16 l0 = __float2bfloat16(v0 - __bfloat162float(h0));
        __nv_bfloat16 l1 = __float2bfloat16(v1 - __bfloat162float(h1));
        __nv_bfloat16 l2 = __float2bfloat16(v2 - __bfloat162float(h2));
        __nv_bfloat16 l3 = __float2bfloat16(v3 - __bfloat162float(h3));
        *(unsigned*)(sCh + r * ldC + n0)       = pack2(h0, h1);
        *(unsigned*)(sCh + (r + 8) * ldC + n0) = pack2(h2, h3);
        *(unsigned*)(sCl + r * ldC + n0)       = pack2(l0, l1);
        *(unsigned*)(sCl + (r + 8) * ldC + n0) = pack2(l2, l3);
    }
}

// ======== final GEMM: relu -> per-column max over tile -> global atomicMax ========
template<int NT, int KW, int WSTR>
__device__ void gemm_out(__nv_bfloat16* sm, int aH, int aL, int ldA,
                         const __nv_bfloat16* __restrict__ gWh,
                         const __nv_bfloat16* __restrict__ gWl,
                         const float* __restrict__ gBias,
                         float* __restrict__ outb, int wsH, int wsL)
{
    constexpr int COUT = NT * 32;
    constexpr int KC = 32, NCH = KW / KC, LDW = 40, NV = 4;
    const int tid  = threadIdx.x;
    const int lane = tid & 31;
    const int w    = tid >> 5;
    const int t    = lane & 3;
    const int mg   = w & 3;
    const int ng   = w >> 2;

    float acc[NT][4];
#pragma unroll
    for (int nt = 0; nt < NT; nt++) {
        int n0 = ng * (NT * 8) + nt * 8 + 2 * t;
        acc[nt][0] = acc[nt][2] = gBias[n0];
        acc[nt][1] = acc[nt][3] = gBias[n0 + 1];
    }

    const int arow = mg * 16 + (lane & 15);
    const int ac8  = ((lane >> 4) & 1) * 8;
    const __nv_bfloat16* pAh = sm + aH + arow * ldA + ac8;
    const __nv_bfloat16* pAl = sm + aL + arow * ldA + ac8;
    const int brow = (lane & 7) + ((lane >> 4) & 1) * 8;
    const int bc8  = ((lane >> 3) & 1) * 8;
    __nv_bfloat16* sWh = sm + wsH;
    __nv_bfloat16* sWl = sm + wsL;

#pragma unroll
    for (int ch = 0; ch < NCH; ch++) {
        __syncthreads();
        for (int idx = tid; idx < COUT * NV; idx += THREADS) {
            int row = idx >> 2, v = (idx & 3) * 8;
            CP16(sptr(sWh + row * LDW + v), gWh + row * WSTR + ch * KC + v);
            CP16(sptr(sWl + row * LDW + v), gWl + row * WSTR + ch * KC + v);
        }
        asm volatile("cp.async.commit_group;");
        asm volatile("cp.async.wait_group 0;" ::: "memory");
        __syncthreads();
#pragma unroll
        for (int ks = 0; ks < KC; ks += 16) {
            unsigned ah[4], al[4];
            ldsm4(ah, pAh + ch * KC + ks);
            ldsm4(al, pAl + ch * KC + ks);
#pragma unroll
            for (int nt = 0; nt < NT; nt += 2) {
                unsigned bh[4], bl[4];
                const __nv_bfloat16* ph = sWh + (ng * (NT * 8) + nt * 8 + brow) * LDW + bc8 + ks;
                const __nv_bfloat16* pl = sWl + (ng * (NT * 8) + nt * 8 + brow) * LDW + bc8 + ks;
                ldsm4(bh, ph);
                ldsm4(bl, pl);
                mma_bf16(acc[nt], ah, bh[0], bh[1]);
                mma_bf16(acc[nt], al, bh[0], bh[1]);
                mma_bf16(acc[nt], ah, bl[0], bl[1]);
                mma_bf16(acc[nt + 1], ah, bh[2], bh[3]);
                mma_bf16(acc[nt + 1], al, bh[2], bh[3]);
                mma_bf16(acc[nt + 1], ah, bl[2], bl[3]);
            }
        }
    }

    // per-column max over the 64-point tile, then atomicMax into out[b][:]
#pragma unroll
    for (int nt = 0; nt < NT; nt++) {
        int n0 = ng * (NT * 8) + nt * 8 + 2 * t;
        float m0 = fmaxf(fmaxf(acc[nt][0], acc[nt][2]), 0.0f);
        float m1 = fmaxf(fmaxf(acc[nt][1], acc[nt][3]), 0.0f);
#pragma unroll
        for (int o = 4; o < 32; o <<= 1) {
            m0 = fmaxf(m0, __shfl_xor_sync(0xffffffff, m0, o));
            m1 = fmaxf(m1, __shfl_xor_sync(0xffffffff, m1, o));
        }
        if ((lane >> 2) == 0) {
            atomicMax((int*)&outb[n0],     __float_as_int(m0));
            atomicMax((int*)&outb[n0 + 1], __float_as_int(m1));
        }
    }
}

// ---------------- feature store + segment-max pool (src = Q planes) ----------------
__device__ void store_and_pool(__nv_bfloat16* sm, const int* s_cl, int nc, int b,
                               unsigned* __restrict__ gfeat, float* __restrict__ gpool,
                               int P0, int qH, int qL, int ldQ)
{
    const int tid = threadIdx.x;
    for (int i = tid; i < TILE * 128; i += THREADS) {
        int p = i >> 7, c = i & 127;
        unsigned h = (unsigned)__bfloat16_as_ushort(sm[qH + p * ldQ + c]);
        unsigned l = (unsigned)__bfloat16_as_ushort(sm[qL + p * ldQ + c]);
        gfeat[(size_t)(P0 + p) * 128 + c] = h | (l << 16);
    }
    float* spool = (float*)sm;   // overlays first region (dead by now)
    for (int i = tid; i < nc * 128; i += THREADS) spool[i] = 0.0f;
    __syncthreads();
    for (int i = tid; i < TILE * 128; i += THREADS) {
        int p = i >> 7, c = i & 127;
        float v = __bfloat162float(sm[qH + p * ldQ + c]) +
                  __bfloat162float(sm[qL + p * ldQ + c]);
        atomicMax((int*)&spool[s_cl[p] * 128 + c], __float_as_int(v));
    }
    __syncthreads();
    for (int i = tid; i < nc * 128; i += THREADS) {
        float v = spool[i];
        if (v > 0.0f)
            atomicMax((int*)&gpool[b * (64 * 128) + i], __float_as_int(v));
    }
}

// ---------------- K0: x(28)->256->64->128, store feat, pool0 ----------------
__global__ void __launch_bounds__(THREADS)
k0_kernel(const float* __restrict__ x, const int* __restrict__ clusters,
          const float* __restrict__ b_in, const float* __restrict__ b1,
          const float* __restrict__ b2,
          unsigned* __restrict__ gfeat, float* __restrict__ gpool)
{
    extern __shared__ __nv_bfloat16 sm[];
    int* s_cl = (int*)(sm + K0_END);
    const int tid = threadIdx.x;
    const int P0  = blockIdx.x * TILE;
    const int b   = P0 / NPTS;

    for (int i = tid; i < TILE * 32; i += THREADS) {
        int p = i >> 5, k = i & 31;
        float v = (k < 28) ? x[(size_t)(P0 + p) * 28 + k] : 0.0f;
        __nv_bfloat16 h = __float2bfloat16(v);
        sm[K0_X_H + p * LD_40 + k] = h;
        sm[K0_X_L + p * LD_40 + k] = __float2bfloat16(v - __bfloat162float(h));
    }
    if (tid < TILE) s_cl[tid] = clusters[P0 + tid];

    gemm2<8, 32, 32, 0>(sm, K0_X_H, K0_X_L, LD_40, g_wh + OFF_WIN, g_wl + OFF_WIN,
                        b_in, nullptr, nullptr, K0_C_H, K0_C_L, LD_264, K0_WS_H, K0_WS_L);
    gemm2<2, 256, 256, 0>(sm, K0_C_H, K0_C_L, LD_264, g_wh + OFF_W1, g_wl + OFF_W1,
                          b1, nullptr, nullptr, K0_M_H, K0_M_L, LD_72, K0_WS_H, K0_WS_L);
    gemm2<4, 64, 64, 0>(sm, K0_M_H, K0_M_L, LD_72, g_wh + OFF_W2, g_wl + OFF_W2,
                        b2, nullptr, nullptr, K0_IO_H, K0_IO_L, LD_136, K0_WS_H, K0_WS_L);
    __syncthreads();

    store_and_pool(sm, s_cl, 16, b, gfeat, gpool, P0, K0_IO_H, K0_IO_L, LD_136);
}

// ---------------- mid blocks: conv3 (P->Q), conv1 (Q+p2l->R), conv2 (R->Q) ----------------
__global__ void __launch_bounds__(THREADS, 2)
mid_kernel(const unsigned* __restrict__ fin, unsigned* __restrict__ fout,
           const int* __restrict__ cl_in, const int* __restrict__ cl_out,
           int nc_in, float* __restrict__ gpool_out, int nc_out,
           const __nv_bfloat16* __restrict__ wh3, const __nv_bfloat16* __restrict__ wl3,
           const float* __restrict__ b3,
           const __nv_bfloat16* __restrict__ wh1, const __nv_bfloat16* __restrict__ wl1,
           const __nv_bfloat16* __restrict__ wh2, const __nv_bfloat16* __restrict__ wl2,
           const float* __restrict__ b2)
{
    extern __shared__ __nv_bfloat16 sm[];
    int* s_cl = (int*)(sm + MF_END);
    const int tid = threadIdx.x;
    const int P0  = blockIdx.x * TILE;
    const int b   = P0 / NPTS;

    for (int i = tid; i < TILE * 128; i += THREADS) {
        int p = i >> 7, c = i & 127;
        unsigned u = fin[(size_t)(P0 + p) * 128 + c];
        sm[MF_P_H + p * LD_136 + c] = __ushort_as_bfloat16((unsigned short)(u & 0xffff));
        sm[MF_P_L + p * LD_136 + c] = __ushort_as_bfloat16((unsigned short)(u >> 16));
    }
    if (tid < TILE) s_cl[tid] = cl_in[P0 + tid];
    else if (tid < 2 * TILE) s_cl[tid] = cl_out[P0 + tid - TILE];

    const float* p2l_b = g_p2l + b * nc_in * 64;

    gemm2<4, 128, 128, 0>(sm, MF_P_H, MF_P_L, LD_136, wh3, wl3, b3,
                          nullptr, nullptr, MF_Q_H, MF_Q_L, LD_136, MF_WS_H, MF_WS_L);
    gemm2<2, 128, 256, 64>(sm, MF_Q_H, MF_Q_L, LD_136, wh1, wl1, nullptr,
                           p2l_b, s_cl, MF_R_H, MF_R_L, LD_72, MF_WS_H, MF_WS_L);
    gemm2<4, 64, 64, 0>(sm, MF_R_H, MF_R_L, LD_72, wh2, wl2, b2,
                        nullptr, nullptr, MF_Q_H, MF_Q_L, LD_136, MF_WS_H, MF_WS_L);
    __syncthreads();

    store_and_pool(sm, s_cl + TILE, nc_out, b, fout, gpool_out, P0, MF_Q_H, MF_Q_L, LD_136);
}

// ---------------- final: conv3 (P->Q), out1 (Q+p2lf->P), out2 (P->max->out) ----------------
__global__ void __launch_bounds__(THREADS, 2)
final_kernel(const unsigned* __restrict__ fin, const int* __restrict__ cl_in,
             const __nv_bfloat16* __restrict__ wh3, const __nv_bfloat16* __restrict__ wl3,
             const float* __restrict__ b3,
             const float* __restrict__ bo2,
             float* __restrict__ out)
{
    extern __shared__ __nv_bfloat16 sm[];
    int* s_cl = (int*)(sm + MF_END);
    const int tid = threadIdx.x;
    const int P0  = blockIdx.x * TILE;
    const int b   = P0 / NPTS;

    for (int i = tid; i < TILE * 128; i += THREADS) {
        int p = i >> 7, c = i & 127;
        unsigned u = fin[(size_t)(P0 + p) * 128 + c];
        sm[MF_P_H + p * LD_136 + c] = __ushort_as_bfloat16((unsigned short)(u & 0xffff));
        sm[MF_P_L + p * LD_136 + c] = __ushort_as_bfloat16((unsigned short)(u >> 16));
    }
    if (tid < TILE) s_cl[tid] = cl_in[P0 + tid];

    const float* p2l_b = g_p2l + b * 64 * 128;

    gemm2<4, 128, 128, 0>(sm, MF_P_H, MF_P_L, LD_136, wh3, wl3, b3,
                          nullptr, nullptr, MF_Q_H, MF_Q_L, LD_136, MF_WS_H, MF_WS_L);
    gemm2<4, 128, 256, 128>(sm, MF_Q_H, MF_Q_L, LD_136, g_wh + OFF_WO1, g_wl + OFF_WO1,
                            nullptr, p2l_b, s_cl, MF_P_H, MF_P_L, LD_136, MF_WS_H, MF_WS_L);
    gemm_out<4, 128, 128>(sm, MF_P_H, MF_P_L, LD_136, g_wh + OFF_WO2, g_wl + OFF_WO2,
                          bo2, out + b * 128, MF_WS_H, MF_WS_L);
}

extern "C" void kernel_launch(void* const* d_in, const int* in_sizes, int n_in,
                              void* d_out, int out_size)
{
    const float* x    = (const float*)d_in[0];
    const int*   cl   = (const int*)  d_in[1];
    const float* w_in = (const float*)d_in[2];
    const float* b_in = (const float*)d_in[3];
    const float* w1   = (const float*)d_in[4];
    const float* b1   = (const float*)d_in[5];
    const float* w2   = (const float*)d_in[6];
    const float* b2   = (const float*)d_in[7];
    const float* w3   = (const float*)d_in[8];
    const float* b3   = (const float*)d_in[9];
    const float* wo1  = (const float*)d_in[10];
    const float* bo1  = (const float*)d_in[11];
    const float* wo2  = (const float*)d_in[12];
    const float* bo2  = (const float*)d_in[13];
    float* out = (float*)d_out;

    void *pa_, *pb_, *pp_, *ph_, *pl_, *pq_;
    cudaGetSymbolAddress(&pa_, g_featA);
    cudaGetSymbolAddress(&pb_, g_featB);
    cudaGetSymbolAddress(&pp_, g_pool);
    cudaGetSymbolAddress(&ph_, g_wh);
    cudaGetSymbolAddress(&pl_, g_wl);
    cudaGetSymbolAddress(&pq_, g_p2l);
    unsigned* fA = (unsigned*)pa_;
    unsigned* fB = (unsigned*)pb_;
    float* pP = (float*)pp_;
    float* pQ = (float*)pq_;
    __nv_bfloat16* wh = (__nv_bfloat16*)ph_;
    __nv_bfloat16* wl = (__nv_bfloat16*)pl_;

    cudaFuncSetAttribute(k0_kernel,    cudaFuncAttributeMaxDynamicSharedMemorySize, SMEM_K0);
    cudaFuncSetAttribute(mid_kernel,   cudaFuncAttributeMaxDynamicSharedMemorySize, SMEM_MF);
    cudaFuncSetAttribute(final_kernel, cudaFuncAttributeMaxDynamicSharedMemorySize, SMEM_MF);

    const int PSTRIDE = BATCH * 64 * 128;

    init_kernel<<<(3 * PSTRIDE + 255) / 256, 256>>>(out);
    convert_all<<<(180224 + 255) / 256, 256>>>(w_in, w1, w2, w3, wo1, wo2);

    k0_kernel<<<NTILES, THREADS, SMEM_K0>>>(x, cl, b_in, b1, b2, fA, pP);

    // p2l for block1: W1b of block 1, pool0 (16 clusters)
    p2l_kernel<<<(8 * 16 * 64 + 255) / 256, 256>>>(w1 + 1 * 64 * 256, b1 + 64, pP, pQ, 16, 64);
    mid_kernel<<<NTILES, THREADS, SMEM_MF>>>(
        fA, fB, cl, cl + BN, 16, pP + PSTRIDE, 32,
        wh + OFF_W3, wl + OFF_W3, b3,
        wh + OFF_W1 + 64 * 256, wl + OFF_W1 + 64 * 256,
        wh + OFF_W2 + 128 * 64, wl + OFF_W2 + 128 * 64, b2 + 128);

    // p2l for block2: W1b of block 2, pool1 (32 clusters)
    p2l_kernel<<<(8 * 32 * 64 + 255) / 256, 256>>>(w1 + 2 * 64 * 256, b1 + 128, pP + PSTRIDE, pQ, 32, 64);
    mid_kernel<<<NTILES, THREADS, SMEM_MF>>>(
        fB, fA, cl + BN, cl + 2 * BN, 32, pP + 2 * PSTRIDE, 64,
        wh + OFF_W3 + 128 * 128, wl + OFF_W3 + 128 * 128, b3 + 128,
        wh + OFF_W1 + 2 * 64 * 256, wl + OFF_W1 + 2 * 64 * 256,
        wh + OFF_W2 + 2 * 128 * 64, wl + OFF_W2 + 2 * 128 * 64, b2 + 2 * 128);

    // p2l for out1: Wo1b, pool2 (64 clusters), J=128
    p2l_kernel<<<(8 * 64 * 128 + 255) / 256, 256>>>(wo1, bo1, pP + 2 * PSTRIDE, pQ, 64, 128);
    final_kernel<<<NTILES, THREADS, SMEM_MF>>>(
        fA, cl + 2 * BN,
        wh + OFF_W3 + 2 * 128 * 128, wl + OFF_W3 + 2 * 128 * 128, b3 + 2 * 128,
        bo2, out);
}

// round 6
// speedup vs baseline: 3.3390x; 1.1309x over previous
#include <cuda_runtime.h>
#include <cuda_bf16.h>

#define BATCH   8
#define NPTS    16384
#define BN      (BATCH * NPTS)
#define TILE    64
#define NTILES  (BN / TILE)        // 2048
#define THREADS 512                // 16 warps

// ---------------- mid/final smem layout (bf16 units) ----------------
// P planes double as conv1-output (R) and pool scratch after they die.
#define MF_P_H  0                  // 64x136
#define MF_P_L  8704
#define MF_Q_H  17408              // 64x136
#define MF_Q_L  26112
#define MF_WS_H 34816              // 128x72 weight chunk (KC=64)
#define MF_WS_L 44032
#define MF_END  53248
#define SMEM_MF (MF_END*2 + 512)   // 107008 B -> 2 CTAs/SM

// ---------------- k0 smem layout ----------------
#define K0_X_H  0                  // 64x40
#define K0_X_L  2560
#define K0_C_H  5120               // 64x264 (256-wide intermediate)
#define K0_C_L  22016
#define K0_M_H  38912              // 64x72
#define K0_M_L  43520
#define K0_IO_H 5120               // overlays C (dead after conv1)
#define K0_IO_L 13824
#define K0_WS_H 48128              // max(256x40, 128x72) = 10240
#define K0_WS_L 58368
#define K0_END  68608
#define SMEM_K0 (K0_END*2 + 512)   // 137728 B -> 1 CTA/SM

#define LD_136 136
#define LD_72  72
#define LD_264 264
#define LD_40  40

// ---------------- global scratch ----------------
__device__ unsigned g_featA[BN * 128];
__device__ unsigned g_featB[BN * 128];
__device__ float    g_pool[3 * BATCH * 64 * 128];
__device__ float    g_p2l[8 * 64 * 128];
__device__ __nv_bfloat16 g_wh[180224];
__device__ __nv_bfloat16 g_wl[180224];

#define OFF_WIN 0        // 256 x 32
#define OFF_W1  8192     // 3 x (64 x 256)
#define OFF_W2  57344    // 3 x (128 x 64)
#define OFF_W3  81920    // 3 x (128 x 128)
#define OFF_WO1 131072   // 128 x 256
#define OFF_WO2 163840   // 128 x 128

__global__ void init_kernel(float* __restrict__ out) {
    int i = blockIdx.x * blockDim.x + threadIdx.x;
    if (i < 3 * BATCH * 64 * 128) g_pool[i] = 0.0f;
    if (i < BATCH * 128) out[i] = 0.0f;
}

__global__ void warm_kernel() {}   // launch-index shim so ncu -s 5 hits mid_kernel

__global__ void convert_all(const float* __restrict__ w_in, const float* __restrict__ w1,
                            const float* __restrict__ w2, const float* __restrict__ w3,
                            const float* __restrict__ wo1, const float* __restrict__ wo2) {
    int i = blockIdx.x * blockDim.x + threadIdx.x;
    if (i >= 180224) return;
    const float* src; int base, cin, kpad;
    if (i < 8192)        { src = w_in; base = 0;      cin = 28;  kpad = 32;  }
    else if (i < 57344)  { src = w1;   base = 8192;   cin = 256; kpad = 256; }
    else if (i < 81920)  { src = w2;   base = 57344;  cin = 64;  kpad = 64;  }
    else if (i < 131072) { src = w3;   base = 81920;  cin = 128; kpad = 128; }
    else if (i < 163840) { src = wo1;  base = 131072; cin = 256; kpad = 256; }
    else                 { src = wo2;  base = 163840; cin = 128; kpad = 128; }
    int j = i - base, r = j / kpad, k = j - r * kpad;
    float v = (k < cin) ? src[r * cin + k] : 0.0f;
    __nv_bfloat16 h = __float2bfloat16(v);
    g_wh[i] = h;
    g_wl[i] = __float2bfloat16(v - __bfloat162float(h));
}

// p2l[b][cl][j] = bias[j] + W[j][128..255] . pool[b][cl][:]  -- block per (b,cl)
__global__ void p2l_kernel(const float* __restrict__ w, const float* __restrict__ bias,
                           const float* __restrict__ pool, float* __restrict__ dst,
                           int ncl, int J) {
    __shared__ float sp[128];
    int bc = blockIdx.x;
    int b = bc / ncl, cl = bc - b * ncl;
    sp[threadIdx.x] = pool[b * 8192 + cl * 128 + threadIdx.x];
    __syncthreads();
    for (int j = threadIdx.x; j < J; j += 128) {
        const float4* wr = (const float4*)(w + j * 256 + 128);
        float s = bias[j];
#pragma unroll
        for (int k = 0; k < 32; k++) {
            float4 wv = wr[k];
            float4 pv = ((const float4*)sp)[k];
            s += wv.x * pv.x + wv.y * pv.y + wv.z * pv.z + wv.w * pv.w;
        }
        dst[bc * J + j] = s;
    }
}

// ---------------- helpers ----------------
__device__ __forceinline__ void mma_bf16(float c[4], const unsigned a[4],
                                         unsigned b0, unsigned b1) {
    asm volatile(
        "mma.sync.aligned.m16n8k16.row.col.f32.bf16.bf16.f32 "
        "{%0,%1,%2,%3}, {%4,%5,%6,%7}, {%8,%9}, {%0,%1,%2,%3};"
        : "+f"(c[0]), "+f"(c[1]), "+f"(c[2]), "+f"(c[3])
        : "r"(a[0]), "r"(a[1]), "r"(a[2]), "r"(a[3]), "r"(b0), "r"(b1));
}
__device__ __forceinline__ unsigned sptr(const void* p) {
    return (unsigned)__cvta_generic_to_shared(p);
}
__device__ __forceinline__ void ldsm4(unsigned r[4], const void* p) {
    asm volatile("ldmatrix.sync.aligned.m8n8.x4.shared.b16 {%0,%1,%2,%3}, [%4];"
                 : "=r"(r[0]), "=r"(r[1]), "=r"(r[2]), "=r"(r[3]) : "r"(sptr(p)));
}
__device__ __forceinline__ unsigned pack2(__nv_bfloat16 x, __nv_bfloat16 y) {
    return ((unsigned)__bfloat16_as_ushort(y) << 16) | (unsigned)__bfloat16_as_ushort(x);
}
#define CP16(d, s) asm volatile("cp.async.cg.shared.global [%0], [%1], 16;" :: "r"(d), "l"(s))

// ================= GEMM + relu + split-bf16 smem writeback =================
// acc init = bias (+ optional per-cluster p2l gather). 16 warps: 4m x 4n groups.
template<int NT, int KW, int KC, int WSTR, int JSTR>
__device__ void gemm2(__nv_bfloat16* sm, int aH, int aL, int ldA,
                      const __nv_bfloat16* __restrict__ gWh,
                      const __nv_bfloat16* __restrict__ gWl,
                      const float* __restrict__ gBias,
                      const float* __restrict__ p2l, const int* __restrict__ s_cl,
                      int cH, int cL, int ldC, int wsH, int wsL)
{
    constexpr int COUT = NT * 32;
    constexpr int NCH  = KW / KC;
    constexpr int LDW  = KC + 8;
    constexpr int NV   = KC / 8;
    const int tid  = threadIdx.x;
    const int lane = tid & 31;
    const int w    = tid >> 5;
    const int g    = lane >> 2;
    const int t    = lane & 3;
    const int mg   = w & 3;
    const int ng   = w >> 2;

    float acc[NT][4];
#pragma unroll
    for (int nt = 0; nt < NT; nt++) {
        int n0 = ng * (NT * 8) + nt * 8 + 2 * t;
        float b0 = gBias ? gBias[n0] : 0.0f;
        float b1 = gBias ? gBias[n0 + 1] : 0.0f;
        if (JSTR) {
            int c0 = s_cl[mg * 16 + g], c1 = s_cl[mg * 16 + g + 8];
            acc[nt][0] = b0 + p2l[c0 * JSTR + n0];
            acc[nt][1] = b1 + p2l[c0 * JSTR + n0 + 1];
            acc[nt][2] = b0 + p2l[c1 * JSTR + n0];
            acc[nt][3] = b1 + p2l[c1 * JSTR + n0 + 1];
        } else {
            acc[nt][0] = b0; acc[nt][1] = b1; acc[nt][2] = b0; acc[nt][3] = b1;
        }
    }

    const int arow = mg * 16 + (lane & 15);
    const int ac8  = ((lane >> 4) & 1) * 8;
    const __nv_bfloat16* pAh = sm + aH + arow * ldA + ac8;
    const __nv_bfloat16* pAl = sm + aL + arow * ldA + ac8;
    const int brow = (lane & 7) + ((lane >> 4) & 1) * 8;
    const int bc8  = ((lane >> 3) & 1) * 8;
    __nv_bfloat16* sWh = sm + wsH;
    __nv_bfloat16* sWl = sm + wsL;

#pragma unroll
    for (int ch = 0; ch < NCH; ch++) {
        __syncthreads();   // WS free / (ch0) prior-stage activations visible
        for (int idx = tid; idx < COUT * NV; idx += THREADS) {
            int row = idx / NV, v = (idx % NV) * 8;
            CP16(sptr(sWh + row * LDW + v), gWh + row * WSTR + ch * KC + v);
            CP16(sptr(sWl + row * LDW + v), gWl + row * WSTR + ch * KC + v);
        }
        asm volatile("cp.async.commit_group;");
        asm volatile("cp.async.wait_group 0;" ::: "memory");
        __syncthreads();
#pragma unroll
        for (int ks = 0; ks < KC; ks += 16) {
            unsigned ah[4], al[4];
            ldsm4(ah, pAh + ch * KC + ks);
            ldsm4(al, pAl + ch * KC + ks);
#pragma unroll
            for (int nt = 0; nt < NT; nt += 2) {
                unsigned bh[4], bl[4];
                const __nv_bfloat16* ph = sWh + (ng * (NT * 8) + nt * 8 + brow) * LDW + bc8 + ks;
                const __nv_bfloat16* pl = sWl + (ng * (NT * 8) + nt * 8 + brow) * LDW + bc8 + ks;
                ldsm4(bh, ph);
                ldsm4(bl, pl);
                mma_bf16(acc[nt], ah, bh[0], bh[1]);
                mma_bf16(acc[nt], al, bh[0], bh[1]);
                mma_bf16(acc[nt], ah, bl[0], bl[1]);
                if (NT > 1) {
                    mma_bf16(acc[nt + 1], ah, bh[2], bh[3]);
                    mma_bf16(acc[nt + 1], al, bh[2], bh[3]);
                    mma_bf16(acc[nt + 1], ah, bl[2], bl[3]);
                }
            }
        }
    }

    __nv_bfloat16* sCh = sm + cH;
    __nv_bfloat16* sCl = sm + cL;
#pragma unroll
    for (int nt = 0; nt < NT; nt++) {
        int n0 = ng * (NT * 8) + nt * 8 + 2 * t;
        int r = mg * 16 + g;
        float v0 = fmaxf(acc[nt][0], 0.0f);
        float v1 = fmaxf(acc[nt][1], 0.0f);
        float v2 = fmaxf(acc[nt][2], 0.0f);
        float v3 = fmaxf(acc[nt][3], 0.0f);
        __nv_bfloat16 h0 = __float2bfloat16(v0), h1 = __float2bfloat16(v1);
        __nv_bfloat16 h2 = __float2bfloat16(v2), h3 = __float2bfloat16(v3);
        __nv_bfloat16 l0 = __float2bfloat16(v0 - __bfloat162float(h0));
        __nv_bfloat16 l1 = __float2bfloat16(v1 - __bfloat162float(h1));
        __nv_bfloat16 l2 = __float2bfloat16(v2 - __bfloat162float(h2));
        __nv_bfloat16 l3 = __float2bfloat16(v3 - __bfloat162float(h3));
        *(unsigned*)(sCh + r * ldC + n0)       = pack2(h0, h1);
        *(unsigned*)(sCh + (r + 8) * ldC + n0) = pack2(h2, h3);
        *(unsigned*)(sCl + r * ldC + n0)       = pack2(l0, l1);
        *(unsigned*)(sCl + (r + 8) * ldC + n0) = pack2(l2, l3);
    }
}

// ======== final GEMM: relu -> per-column tile max -> global atomicMax ========
template<int NT, int KW, int KC, int WSTR>
__device__ void gemm_out(__nv_bfloat16* sm, int aH, int aL, int ldA,
                         const __nv_bfloat16* __restrict__ gWh,
                         const __nv_bfloat16* __restrict__ gWl,
                         const float* __restrict__ gBias,
                         float* __restrict__ outb, int wsH, int wsL)
{
    constexpr int COUT = NT * 32;
    constexpr int NCH = KW / KC, LDW = KC + 8, NV = KC / 8;
    const int tid  = threadIdx.x;
    const int lane = tid & 31;
    const int w    = tid >> 5;
    const int t    = lane & 3;
    const int mg   = w & 3;
    const int ng   = w >> 2;

    float acc[NT][4];
#pragma unroll
    for (int nt = 0; nt < NT; nt++) {
        int n0 = ng * (NT * 8) + nt * 8 + 2 * t;
        acc[nt][0] = acc[nt][2] = gBias[n0];
        acc[nt][1] = acc[nt][3] = gBias[n0 + 1];
    }

    const int arow = mg * 16 + (lane & 15);
    const int ac8  = ((lane >> 4) & 1) * 8;
    const __nv_bfloat16* pAh = sm + aH + arow * ldA + ac8;
    const __nv_bfloat16* pAl = sm + aL + arow * ldA + ac8;
    const int brow = (lane & 7) + ((lane >> 4) & 1) * 8;
    const int bc8  = ((lane >> 3) & 1) * 8;
    __nv_bfloat16* sWh = sm + wsH;
    __nv_bfloat16* sWl = sm + wsL;

#pragma unroll
    for (int ch = 0; ch < NCH; ch++) {
        __syncthreads();
        for (int idx = tid; idx < COUT * NV; idx += THREADS) {
            int row = idx / NV, v = (idx % NV) * 8;
            CP16(sptr(sWh + row * LDW + v), gWh + row * WSTR + ch * KC + v);
            CP16(sptr(sWl + row * LDW + v), gWl + row * WSTR + ch * KC + v);
        }
        asm volatile("cp.async.commit_group;");
        asm volatile("cp.async.wait_group 0;" ::: "memory");
        __syncthreads();
#pragma unroll
        for (int ks = 0; ks < KC; ks += 16) {
            unsigned ah[4], al[4];
            ldsm4(ah, pAh + ch * KC + ks);
            ldsm4(al, pAl + ch * KC + ks);
#pragma unroll
            for (int nt = 0; nt < NT; nt += 2) {
                unsigned bh[4], bl[4];
                const __nv_bfloat16* ph = sWh + (ng * (NT * 8) + nt * 8 + brow) * LDW + bc8 + ks;
                const __nv_bfloat16* pl = sWl + (ng * (NT * 8) + nt * 8 + brow) * LDW + bc8 + ks;
                ldsm4(bh, ph);
                ldsm4(bl, pl);
                mma_bf16(acc[nt], ah, bh[0], bh[1]);
                mma_bf16(acc[nt], al, bh[0], bh[1]);
                mma_bf16(acc[nt], ah, bl[0], bl[1]);
                mma_bf16(acc[nt + 1], ah, bh[2], bh[3]);
                mma_bf16(acc[nt + 1], al, bh[2], bh[3]);
                mma_bf16(acc[nt + 1], ah, bl[2], bl[3]);
            }
        }
    }

#pragma unroll
    for (int nt = 0; nt < NT; nt++) {
        int n0 = ng * (NT * 8) + nt * 8 + 2 * t;
        float m0 = fmaxf(fmaxf(acc[nt][0], acc[nt][2]), 0.0f);
        float m1 = fmaxf(fmaxf(acc[nt][1], acc[nt][3]), 0.0f);
#pragma unroll
        for (int o = 4; o < 32; o <<= 1) {
            m0 = fmaxf(m0, __shfl_xor_sync(0xffffffff, m0, o));
            m1 = fmaxf(m1, __shfl_xor_sync(0xffffffff, m1, o));
        }
        if ((lane >> 2) == 0) {
            atomicMax((int*)&outb[n0],     __float_as_int(m0));
            atomicMax((int*)&outb[n0 + 1], __float_as_int(m1));
        }
    }
}

// ---------------- feature store + segment-max pool ----------------
__device__ void store_and_pool(__nv_bfloat16* sm, const int* s_cl, int nc, int b,
                               unsigned* __restrict__ gfeat, float* __restrict__ gpool,
                               int P0, int qH, int qL, int ldQ)
{
    const int tid = threadIdx.x;
    for (int i = tid; i < TILE * 128; i += THREADS) {
        int p = i >> 7, c = i & 127;
        unsigned h = (unsigned)__bfloat16_as_ushort(sm[qH + p * ldQ + c]);
        unsigned l = (unsigned)__bfloat16_as_ushort(sm[qL + p * ldQ + c]);
        gfeat[(size_t)(P0 + p) * 128 + c] = h | (l << 16);
    }
    float* spool = (float*)sm;   // overlays dead leading region
    for (int i = tid; i < nc * 128; i += THREADS) spool[i] = 0.0f;
    __syncthreads();
    for (int i = tid; i < TILE * 128; i += THREADS) {
        int p = i >> 7, c = i & 127;
        float v = __bfloat162float(sm[qH + p * ldQ + c]) +
                  __bfloat162float(sm[qL + p * ldQ + c]);
        atomicMax((int*)&spool[s_cl[p] * 128 + c], __float_as_int(v));
    }
    __syncthreads();
    for (int i = tid; i < nc * 128; i += THREADS) {
        float v = spool[i];
        if (v > 0.0f)
            atomicMax((int*)&gpool[b * (64 * 128) + i], __float_as_int(v));
    }
}

// ---------------- K0: x(28)->256->64->128, store feat, pool0 ----------------
__global__ void __launch_bounds__(THREADS)
k0_kernel(const float* __restrict__ x, const int* __restrict__ clusters,
          const float* __restrict__ b_in, const float* __restrict__ b1,
          const float* __restrict__ b2,
          unsigned* __restrict__ gfeat, float* __restrict__ gpool)
{
    extern __shared__ __nv_bfloat16 sm[];
    int* s_cl = (int*)(sm + K0_END);
    const int tid = threadIdx.x;
    const int P0  = blockIdx.x * TILE;
    const int b   = P0 / NPTS;

    for (int i = tid; i < TILE * 32; i += THREADS) {
        int p = i >> 5, k = i & 31;
        float v = (k < 28) ? x[(size_t)(P0 + p) * 28 + k] : 0.0f;
        __nv_bfloat16 h = __float2bfloat16(v);
        sm[K0_X_H + p * LD_40 + k] = h;
        sm[K0_X_L + p * LD_40 + k] = __float2bfloat16(v - __bfloat162float(h));
    }
    if (tid < TILE) s_cl[tid] = clusters[P0 + tid];

    gemm2<8, 32, 32, 32, 0>(sm, K0_X_H, K0_X_L, LD_40, g_wh + OFF_WIN, g_wl + OFF_WIN,
                            b_in, nullptr, nullptr, K0_C_H, K0_C_L, LD_264, K0_WS_H, K0_WS_L);
    gemm2<2, 256, 64, 256, 0>(sm, K0_C_H, K0_C_L, LD_264, g_wh + OFF_W1, g_wl + OFF_W1,
                              b1, nullptr, nullptr, K0_M_H, K0_M_L, LD_72, K0_WS_H, K0_WS_L);
    gemm2<4, 64, 64, 64, 0>(sm, K0_M_H, K0_M_L, LD_72, g_wh + OFF_W2, g_wl + OFF_W2,
                            b2, nullptr, nullptr, K0_IO_H, K0_IO_L, LD_136, K0_WS_H, K0_WS_L);
    __syncthreads();

    store_and_pool(sm, s_cl, 16, b, gfeat, gpool, P0, K0_IO_H, K0_IO_L, LD_136);
}

// ---------------- mid: conv3 (P->Q), conv1 (Q+p2l->R=P), conv2 (R->Q) ----------------
__global__ void __launch_bounds__(THREADS, 2)
mid_kernel(const unsigned* __restrict__ fin, unsigned* __restrict__ fout,
           const int* __restrict__ cl_in, const int* __restrict__ cl_out,
           int nc_in, float* __restrict__ gpool_out, int nc_out,
           const __nv_bfloat16* __restrict__ wh3, const __nv_bfloat16* __restrict__ wl3,
           const float* __restrict__ b3,
           const __nv_bfloat16* __restrict__ wh1, const __nv_bfloat16* __restrict__ wl1,
           const __nv_bfloat16* __restrict__ wh2, const __nv_bfloat16* __restrict__ wl2,
           const float* __restrict__ b2)
{
    extern __shared__ __nv_bfloat16 sm[];
    int* s_cl = (int*)(sm + MF_END);
    const int tid = threadIdx.x;
    const int P0  = blockIdx.x * TILE;
    const int b   = P0 / NPTS;

    for (int i = tid; i < TILE * 128; i += THREADS) {
        int p = i >> 7, c = i & 127;
        unsigned u = fin[(size_t)(P0 + p) * 128 + c];
        sm[MF_P_H + p * LD_136 + c] = __ushort_as_bfloat16((unsigned short)(u & 0xffff));
        sm[MF_P_L + p * LD_136 + c] = __ushort_as_bfloat16((unsigned short)(u >> 16));
    }
    if (tid < TILE) s_cl[tid] = cl_in[P0 + tid];
    else if (tid < 2 * TILE) s_cl[tid] = cl_out[P0 + tid - TILE];

    const float* p2l_b = g_p2l + b * nc_in * 64;

    gemm2<4, 128, 64, 128, 0>(sm, MF_P_H, MF_P_L, LD_136, wh3, wl3, b3,
                              nullptr, nullptr, MF_Q_H, MF_Q_L, LD_136, MF_WS_H, MF_WS_L);
    gemm2<2, 128, 64, 256, 64>(sm, MF_Q_H, MF_Q_L, LD_136, wh1, wl1, nullptr,
                               p2l_b, s_cl, MF_P_H, MF_P_L, LD_72, MF_WS_H, MF_WS_L);
    gemm2<4, 64, 64, 64, 0>(sm, MF_P_H, MF_P_L, LD_72, wh2, wl2, b2,
                            nullptr, nullptr, MF_Q_H, MF_Q_L, LD_136, MF_WS_H, MF_WS_L);
    __syncthreads();

    store_and_pool(sm, s_cl + TILE, nc_out, b, fout, gpool_out, P0, MF_Q_H, MF_Q_L, LD_136);
}

// ---------------- final: conv3 (P->Q), out1 (Q+p2l->P), out2 (P->max->out) ----------------
__global__ void __launch_bounds__(THREADS, 2)
final_kernel(const unsigned* __restrict__ fin, const int* __restrict__ cl_in,
             const __nv_bfloat16* __restrict__ wh3, const __nv_bfloat16* __restrict__ wl3,
             const float* __restrict__ b3,
             const float* __restrict__ bo2,
             float* __restrict__ out)
{
    extern __shared__ __nv_bfloat16 sm[];
    int* s_cl = (int*)(sm + MF_END);
    const int tid = threadIdx.x;
    const int P0  = blockIdx.x * TILE;
    const int b   = P0 / NPTS;

    for (int i = tid; i < TILE * 128; i += THREADS) {
        int p = i >> 7, c = i & 127;
        unsigned u = fin[(size_t)(P0 + p) * 128 + c];
        sm[MF_P_H + p * LD_136 + c] = __ushort_as_bfloat16((unsigned short)(u & 0xffff));
        sm[MF_P_L + p * LD_136 + c] = __ushort_as_bfloat16((unsigned short)(u >> 16));
    }
    if (tid < TILE) s_cl[tid] = cl_in[P0 + tid];

    const float* p2l_b = g_p2l + b * 64 * 128;

    gemm2<4, 128, 64, 128, 0>(sm, MF_P_H, MF_P_L, LD_136, wh3, wl3, b3,
                              nullptr, nullptr, MF_Q_H, MF_Q_L, LD_136, MF_WS_H, MF_WS_L);
    gemm2<4, 128, 64, 256, 128>(sm, MF_Q_H, MF_Q_L, LD_136, g_wh + OFF_WO1, g_wl + OFF_WO1,
                                nullptr, p2l_b, s_cl, MF_P_H, MF_P_L, LD_136, MF_WS_H, MF_WS_L);
    gemm_out<4, 128, 64, 128>(sm, MF_P_H, MF_P_L, LD_136, g_wh + OFF_WO2, g_wl + OFF_WO2,
                              bo2, out + b * 128, MF_WS_H, MF_WS_L);
}

extern "C" void kernel_launch(void* const* d_in, const int* in_sizes, int n_in,
                              void* d_out, int out_size)
{
    const float* x    = (const float*)d_in[0];
    const int*   cl   = (const int*)  d_in[1];
    const float* w_in = (const float*)d_in[2];
    const float* b_in = (const float*)d_in[3];
    const float* w1   = (const float*)d_in[4];
    const float* b1   = (const float*)d_in[5];
    const float* w2   = (const float*)d_in[6];
    const float* b2   = (const float*)d_in[7];
    const float* w3   = (const float*)d_in[8];
    const float* b3   = (const float*)d_in[9];
    const float* wo1  = (const float*)d_in[10];
    const float* bo1  = (const float*)d_in[11];
    const float* wo2  = (const float*)d_in[12];
    const float* bo2  = (const float*)d_in[13];
    float* out = (float*)d_out;

    void *pa_, *pb_, *pp_, *ph_, *pl_, *pq_;
    cudaGetSymbolAddress(&pa_, g_featA);
    cudaGetSymbolAddress(&pb_, g_featB);
    cudaGetSymbolAddress(&pp_, g_pool);
    cudaGetSymbolAddress(&ph_, g_wh);
    cudaGetSymbolAddress(&pl_, g_wl);
    cudaGetSymbolAddress(&pq_, g_p2l);
    unsigned* fA = (unsigned*)pa_;
    unsigned* fB = (unsigned*)pb_;
    float* pP = (float*)pp_;
    float* pQ = (float*)pq_;
    __nv_bfloat16* wh = (__nv_bfloat16*)ph_;
    __nv_bfloat16* wl = (__nv_bfloat16*)pl_;

    cudaFuncSetAttribute(k0_kernel,    cudaFuncAttributeMaxDynamicSharedMemorySize, SMEM_K0);
    cudaFuncSetAttribute(mid_kernel,   cudaFuncAttributeMaxDynamicSharedMemorySize, SMEM_MF);
    cudaFuncSetAttribute(final_kernel, cudaFuncAttributeMaxDynamicSharedMemorySize, SMEM_MF);

    const int PSTRIDE = BATCH * 64 * 128;

    init_kernel<<<(3 * PSTRIDE + 255) / 256, 256>>>(out);
    convert_all<<<(180224 + 255) / 256, 256>>>(w_in, w1, w2, w3, wo1, wo2);
    warm_kernel<<<1, 32>>>();

    k0_kernel<<<NTILES, THREADS, SMEM_K0>>>(x, cl, b_in, b1, b2, fA, pP);

    p2l_kernel<<<8 * 16, 128>>>(w1 + 1 * 64 * 256, b1 + 64, pP, pQ, 16, 64);
    mid_kernel<<<NTILES, THREADS, SMEM_MF>>>(
        fA, fB, cl, cl + BN, 16, pP + PSTRIDE, 32,
        wh + OFF_W3, wl + OFF_W3, b3,
        wh + OFF_W1 + 64 * 256, wl + OFF_W1 + 64 * 256,
        wh + OFF_W2 + 128 * 64, wl + OFF_W2 + 128 * 64, b2 + 128);

    p2l_kernel<<<8 * 32, 128>>>(w1 + 2 * 64 * 256, b1 + 128, pP + PSTRIDE, pQ, 32, 64);
    mid_kernel<<<NTILES, THREADS, SMEM_MF>>>(
        fB, fA, cl + BN, cl + 2 * BN, 32, pP + 2 * PSTRIDE, 64,
        wh + OFF_W3 + 128 * 128, wl + OFF_W3 + 128 * 128, b3 + 128,
        wh + OFF_W1 + 2 * 64 * 256, wl + OFF_W1 + 2 * 64 * 256,
        wh + OFF_W2 + 2 * 128 * 64, wl + OFF_W2 + 2 * 128 * 64, b2 + 2 * 128);

    p2l_kernel<<<8 * 64, 128>>>(wo1, bo1, pP + 2 * PSTRIDE, pQ, 64, 128);
    final_kernel<<<NTILES, THREADS, SMEM_MF>>>(
        fA, cl + 2 * BN,
        wh + OFF_W3 + 2 * 128 * 128, wl + OFF_W3 + 2 * 128 * 128, b3 + 2 * 128,
        bo2, out);
}

// round 7
// speedup vs baseline: 3.6644x; 1.0975x over previous
#include <cuda_runtime.h>
#include <cuda_bf16.h>

#define BATCH   8
#define NPTS    16384
#define BN      (BATCH * NPTS)
#define TILE    64
#define NTILES  (BN / TILE)        // 2048
#define THREADS 512                // 16 warps

// ---------------- mid/final smem layout (bf16 units) ----------------
#define MF_P_H  0                  // 64x136
#define MF_P_L  8704
#define MF_Q_H  17408              // 64x136
#define MF_Q_L  26112
#define MF_WS_H 34816              // 128x72 weight chunk (KC=64)
#define MF_WS_L 44032
#define MF_END  53248
#define SMEM_MF (MF_END*2 + 512)   // 107008 B -> 2 CTAs/SM

// ---------------- k0 smem layout (split-K restructure) ----------------
#define K0_X_H  0                  // 64x40
#define K0_X_L  2560
#define K0_C_H  5120               // 64x136 (half of mlp_in output; reused)
#define K0_C_L  13824
#define K0_M_H  22528              // 64x72 (conv1 out)
#define K0_M_L  27136
#define K0_IO_H 5120               // conv2 out overlays C (dead after conv1)
#define K0_IO_L 13824
#define K0_WS_H 31744              // 128x72 max
#define K0_WS_L 40960
#define K0_END  50176
#define SMEM_K0 (K0_END*2 + 512)   // 100864 B -> 2 CTAs/SM

#define LD_136 136
#define LD_72  72
#define LD_40  40

// ---------------- global scratch ----------------
__device__ unsigned g_featA[BN * 128];
__device__ unsigned g_featB[BN * 128];
__device__ float    g_pool[3 * BATCH * 64 * 128];
__device__ float    g_p2l[8 * 64 * 128];
__device__ __nv_bfloat16 g_wh[180224];
__device__ __nv_bfloat16 g_wl[180224];

#define OFF_WIN 0        // 256 x 32
#define OFF_W1  8192     // 3 x (64 x 256)
#define OFF_W2  57344    // 3 x (128 x 64)
#define OFF_W3  81920    // 3 x (128 x 128)
#define OFF_WO1 131072   // 128 x 256
#define OFF_WO2 163840   // 128 x 128

__global__ void init_kernel(float* __restrict__ out) {
    int i = blockIdx.x * blockDim.x + threadIdx.x;
    if (i < 3 * BATCH * 64 * 128) g_pool[i] = 0.0f;
    if (i < BATCH * 128) out[i] = 0.0f;
}

__global__ void warm_kernel() {}

__global__ void convert_all(const float* __restrict__ w_in, const float* __restrict__ w1,
                            const float* __restrict__ w2, const float* __restrict__ w3,
                            const float* __restrict__ wo1, const float* __restrict__ wo2) {
    int i = blockIdx.x * blockDim.x + threadIdx.x;
    if (i >= 180224) return;
    const float* src; int base, cin, kpad;
    if (i < 8192)        { src = w_in; base = 0;      cin = 28;  kpad = 32;  }
    else if (i < 57344)  { src = w1;   base = 8192;   cin = 256; kpad = 256; }
    else if (i < 81920)  { src = w2;   base = 57344;  cin = 64;  kpad = 64;  }
    else if (i < 131072) { src = w3;   base = 81920;  cin = 128; kpad = 128; }
    else if (i < 163840) { src = wo1;  base = 131072; cin = 256; kpad = 256; }
    else                 { src = wo2;  base = 163840; cin = 128; kpad = 128; }
    int j = i - base, r = j / kpad, k = j - r * kpad;
    float v = (k < cin) ? src[r * cin + k] : 0.0f;
    __nv_bfloat16 h = __float2bfloat16(v);
    g_wh[i] = h;
    g_wl[i] = __float2bfloat16(v - __bfloat162float(h));
}

// p2l[b][cl][j] = bias[j] + W[j][128..255] . pool[b][cl][:]
__global__ void p2l_kernel(const float* __restrict__ w, const float* __restrict__ bias,
                           const float* __restrict__ pool, float* __restrict__ dst,
                           int ncl, int J) {
    __shared__ float sp[128];
    int bc = blockIdx.x;
    int b = bc / ncl, cl = bc - b * ncl;
    sp[threadIdx.x] = pool[b * 8192 + cl * 128 + threadIdx.x];
    __syncthreads();
    for (int j = threadIdx.x; j < J; j += 128) {
        const float4* wr = (const float4*)(w + j * 256 + 128);
        float s = bias[j];
#pragma unroll
        for (int k = 0; k < 32; k++) {
            float4 wv = wr[k];
            float4 pv = ((const float4*)sp)[k];
            s += wv.x * pv.x + wv.y * pv.y + wv.z * pv.z + wv.w * pv.w;
        }
        dst[bc * J + j] = s;
    }
}

// ---------------- helpers ----------------
__device__ __forceinline__ void mma_bf16(float c[4], const unsigned a[4],
                                         unsigned b0, unsigned b1) {
    asm volatile(
        "mma.sync.aligned.m16n8k16.row.col.f32.bf16.bf16.f32 "
        "{%0,%1,%2,%3}, {%4,%5,%6,%7}, {%8,%9}, {%0,%1,%2,%3};"
        : "+f"(c[0]), "+f"(c[1]), "+f"(c[2]), "+f"(c[3])
        : "r"(a[0]), "r"(a[1]), "r"(a[2]), "r"(a[3]), "r"(b0), "r"(b1));
}
__device__ __forceinline__ unsigned sptr(const void* p) {
    return (unsigned)__cvta_generic_to_shared(p);
}
__device__ __forceinline__ void ldsm4(unsigned r[4], const void* p) {
    asm volatile("ldmatrix.sync.aligned.m8n8.x4.shared.b16 {%0,%1,%2,%3}, [%4];"
                 : "=r"(r[0]), "=r"(r[1]), "=r"(r[2]), "=r"(r[3]) : "r"(sptr(p)));
}
__device__ __forceinline__ unsigned pack2(__nv_bfloat16 x, __nv_bfloat16 y) {
    return ((unsigned)__bfloat16_as_ushort(y) << 16) | (unsigned)__bfloat16_as_ushort(x);
}
#define CP16(d, s) asm volatile("cp.async.cg.shared.global [%0], [%1], 16;" :: "r"(d), "l"(s))

// ================= GEMM mainloop (accumulates into caller's acc) =================
// 16 warps: 4 m-groups x 4 n-groups. Opens with __syncthreads (prior stage visible).
template<int NT, int KW, int KC, int WSTR>
__device__ __forceinline__ void gemm_core(float (*acc)[4], __nv_bfloat16* sm,
                                          int aH, int aL, int ldA,
                                          const __nv_bfloat16* __restrict__ gWh,
                                          const __nv_bfloat16* __restrict__ gWl,
                                          int wsH, int wsL)
{
    constexpr int COUT = NT * 32;
    constexpr int NCH  = KW / KC;
    constexpr int LDW  = KC + 8;
    constexpr int NV   = KC / 8;
    const int tid  = threadIdx.x;
    const int lane = tid & 31;
    const int w    = tid >> 5;
    const int mg   = w & 3;
    const int ng   = w >> 2;

    const int arow = mg * 16 + (lane & 15);
    const int ac8  = ((lane >> 4) & 1) * 8;
    const __nv_bfloat16* pAh = sm + aH + arow * ldA + ac8;
    const __nv_bfloat16* pAl = sm + aL + arow * ldA + ac8;
    const int brow = (lane & 7) + ((lane >> 4) & 1) * 8;
    const int bc8  = ((lane >> 3) & 1) * 8;
    __nv_bfloat16* sWh = sm + wsH;
    __nv_bfloat16* sWl = sm + wsL;

#pragma unroll
    for (int ch = 0; ch < NCH; ch++) {
        __syncthreads();   // WS free / (ch0) prior-stage activations visible
        for (int idx = tid; idx < COUT * NV; idx += THREADS) {
            int row = idx / NV, v = (idx % NV) * 8;
            CP16(sptr(sWh + row * LDW + v), gWh + row * WSTR + ch * KC + v);
            CP16(sptr(sWl + row * LDW + v), gWl + row * WSTR + ch * KC + v);
        }
        asm volatile("cp.async.commit_group;");
        asm volatile("cp.async.wait_group 0;" ::: "memory");
        __syncthreads();
#pragma unroll
        for (int ks = 0; ks < KC; ks += 16) {
            unsigned ah[4], al[4];
            ldsm4(ah, pAh + ch * KC + ks);
            ldsm4(al, pAl + ch * KC + ks);
#pragma unroll
            for (int nt = 0; nt < NT; nt += 2) {
                unsigned bh[4], bl[4];
                const __nv_bfloat16* ph = sWh + (ng * (NT * 8) + nt * 8 + brow) * LDW + bc8 + ks;
                const __nv_bfloat16* pl = sWl + (ng * (NT * 8) + nt * 8 + brow) * LDW + bc8 + ks;
                ldsm4(bh, ph);
                ldsm4(bl, pl);
                mma_bf16(acc[nt], ah, bh[0], bh[1]);
                mma_bf16(acc[nt], al, bh[0], bh[1]);
                mma_bf16(acc[nt], ah, bl[0], bl[1]);
                mma_bf16(acc[nt + 1], ah, bh[2], bh[3]);
                mma_bf16(acc[nt + 1], al, bh[2], bh[3]);
                mma_bf16(acc[nt + 1], ah, bl[2], bl[3]);
            }
        }
    }
}

// relu + split-bf16 smem writeback
template<int NT>
__device__ __forceinline__ void epilogue_relu(float (*acc)[4], __nv_bfloat16* sm,
                                              int cH, int cL, int ldC)
{
    const int tid  = threadIdx.x;
    const int lane = tid & 31;
    const int w    = tid >> 5;
    const int g    = lane >> 2;
    const int t    = lane & 3;
    const int mg   = w & 3;
    const int ng   = w >> 2;
    __nv_bfloat16* sCh = sm + cH;
    __nv_bfloat16* sCl = sm + cL;
#pragma unroll
    for (int nt = 0; nt < NT; nt++) {
        int n0 = ng * (NT * 8) + nt * 8 + 2 * t;
        int r = mg * 16 + g;
        float v0 = fmaxf(acc[nt][0], 0.0f);
        float v1 = fmaxf(acc[nt][1], 0.0f);
        float v2 = fmaxf(acc[nt][2], 0.0f);
        float v3 = fmaxf(acc[nt][3], 0.0f);
        __nv_bfloat16 h0 = __float2bfloat16(v0), h1 = __float2bfloat16(v1);
        __nv_bfloat16 h2 = __float2bfloat16(v2), h3 = __float2bfloat16(v3);
        __nv_bfloat16 l0 = __float2bfloat16(v0 - __bfloat162float(h0));
        __nv_bfloat16 l1 = __float2bfloat16(v1 - __bfloat162float(h1));
        __nv_bfloat16 l2 = __float2bfloat16(v2 - __bfloat162float(h2));
        __nv_bfloat16 l3 = __float2bfloat16(v3 - __bfloat162float(h3));
        *(unsigned*)(sCh + r * ldC + n0)       = pack2(h0, h1);
        *(unsigned*)(sCh + (r + 8) * ldC + n0) = pack2(h2, h3);
        *(unsigned*)(sCl + r * ldC + n0)       = pack2(l0, l1);
        *(unsigned*)(sCl + (r + 8) * ldC + n0) = pack2(l2, l3);
    }
}

// acc init: bias (+ optional per-cluster p2l gather)
template<int NT, int JSTR>
__device__ __forceinline__ void init_acc(float (*acc)[4], const float* gBias,
                                         const float* p2l, const int* s_cl)
{
    const int tid  = threadIdx.x;
    const int lane = tid & 31;
    const int w    = tid >> 5;
    const int g    = lane >> 2;
    const int t    = lane & 3;
    const int mg   = w & 3;
    const int ng   = w >> 2;
#pragma unroll
    for (int nt = 0; nt < NT; nt++) {
        int n0 = ng * (NT * 8) + nt * 8 + 2 * t;
        float b0 = gBias ? gBias[n0] : 0.0f;
        float b1 = gBias ? gBias[n0 + 1] : 0.0f;
        if (JSTR) {
            int c0 = s_cl[mg * 16 + g], c1 = s_cl[mg * 16 + g + 8];
            acc[nt][0] = b0 + p2l[c0 * JSTR + n0];
            acc[nt][1] = b1 + p2l[c0 * JSTR + n0 + 1];
            acc[nt][2] = b0 + p2l[c1 * JSTR + n0];
            acc[nt][3] = b1 + p2l[c1 * JSTR + n0 + 1];
        } else {
            acc[nt][0] = b0; acc[nt][1] = b1; acc[nt][2] = b0; acc[nt][3] = b1;
        }
    }
}

template<int NT, int KW, int KC, int WSTR, int JSTR>
__device__ void gemm2(__nv_bfloat16* sm, int aH, int aL, int ldA,
                      const __nv_bfloat16* __restrict__ gWh,
                      const __nv_bfloat16* __restrict__ gWl,
                      const float* __restrict__ gBias,
                      const float* __restrict__ p2l, const int* __restrict__ s_cl,
                      int cH, int cL, int ldC, int wsH, int wsL)
{
    float acc[NT][4];
    init_acc<NT, JSTR>(acc, gBias, p2l, s_cl);
    gemm_core<NT, KW, KC, WSTR>(acc, sm, aH, aL, ldA, gWh, gWl, wsH, wsL);
    epilogue_relu<NT>(acc, sm, cH, cL, ldC);
}

// final GEMM: relu -> per-column tile max -> global atomicMax
template<int NT, int KW, int KC, int WSTR>
__device__ void gemm_out(__nv_bfloat16* sm, int aH, int aL, int ldA,
                         const __nv_bfloat16* __restrict__ gWh,
                         const __nv_bfloat16* __restrict__ gWl,
                         const float* __restrict__ gBias,
                         float* __restrict__ outb, int wsH, int wsL)
{
    const int lane = threadIdx.x & 31;
    const int t    = lane & 3;
    const int ng   = (threadIdx.x >> 5) >> 2;

    float acc[NT][4];
    init_acc<NT, 0>(acc, gBias, nullptr, nullptr);
    gemm_core<NT, KW, KC, WSTR>(acc, sm, aH, aL, ldA, gWh, gWl, wsH, wsL);

#pragma unroll
    for (int nt = 0; nt < NT; nt++) {
        int n0 = ng * (NT * 8) + nt * 8 + 2 * t;
        float m0 = fmaxf(fmaxf(acc[nt][0], acc[nt][2]), 0.0f);
        float m1 = fmaxf(fmaxf(acc[nt][1], acc[nt][3]), 0.0f);
#pragma unroll
        for (int o = 4; o < 32; o <<= 1) {
            m0 = fmaxf(m0, __shfl_xor_sync(0xffffffff, m0, o));
            m1 = fmaxf(m1, __shfl_xor_sync(0xffffffff, m1, o));
        }
        if ((lane >> 2) == 0) {
            atomicMax((int*)&outb[n0],     __float_as_int(m0));
            atomicMax((int*)&outb[n0 + 1], __float_as_int(m1));
        }
    }
}

// ---------------- feature store + segment-max pool ----------------
__device__ void store_and_pool(__nv_bfloat16* sm, const int* s_cl, int nc, int b,
                               unsigned* __restrict__ gfeat, float* __restrict__ gpool,
                               int P0, int qH, int qL, int ldQ)
{
    const int tid = threadIdx.x;
    for (int i = tid; i < TILE * 128; i += THREADS) {
        int p = i >> 7, c = i & 127;
        unsigned h = (unsigned)__bfloat16_as_ushort(sm[qH + p * ldQ + c]);
        unsigned l = (unsigned)__bfloat16_as_ushort(sm[qL + p * ldQ + c]);
        gfeat[(size_t)(P0 + p) * 128 + c] = h | (l << 16);
    }
    float* spool = (float*)sm;   // overlays dead leading region
    for (int i = tid; i < nc * 128; i += THREADS) spool[i] = 0.0f;
    __syncthreads();
    for (int i = tid; i < TILE * 128; i += THREADS) {
        int p = i >> 7, c = i & 127;
        float v = __bfloat162float(sm[qH + p * ldQ + c]) +
                  __bfloat162float(sm[qL + p * ldQ + c]);
        atomicMax((int*)&spool[s_cl[p] * 128 + c], __float_as_int(v));
    }
    __syncthreads();
    for (int i = tid; i < nc * 128; i += THREADS) {
        float v = spool[i];
        if (v > 0.0f)
            atomicMax((int*)&gpool[b * (64 * 128) + i], __float_as_int(v));
    }
}

// ---------------- K0: split-K restructure ----------------
// WIN_a (x->C cols 0..127), conv1 partial K1, WIN_b (x->C cols 128..255),
// conv1 partial K2 -> M; conv2 (M->IO); store+pool0.
__global__ void __launch_bounds__(THREADS, 2)
k0_kernel(const float* __restrict__ x, const int* __restrict__ clusters,
          const float* __restrict__ b_in, const float* __restrict__ b1,
          const float* __restrict__ b2,
          unsigned* __restrict__ gfeat, float* __restrict__ gpool)
{
    extern __shared__ __nv_bfloat16 sm[];
    int* s_cl = (int*)(sm + K0_END);
    const int tid = threadIdx.x;
    const int P0  = blockIdx.x * TILE;
    const int b   = P0 / NPTS;

    for (int i = tid; i < TILE * 32; i += THREADS) {
        int p = i >> 5, k = i & 31;
        float v = (k < 28) ? x[(size_t)(P0 + p) * 28 + k] : 0.0f;
        __nv_bfloat16 h = __float2bfloat16(v);
        sm[K0_X_H + p * LD_40 + k] = h;
        sm[K0_X_L + p * LD_40 + k] = __float2bfloat16(v - __bfloat162float(h));
    }
    if (tid < TILE) s_cl[tid] = clusters[P0 + tid];

    float acc1[2][4];                                  // conv1 accumulators
    init_acc<2, 0>(acc1, b1, nullptr, nullptr);

    // WIN first half: w_in rows 0..127 -> C
    gemm2<4, 32, 32, 32, 0>(sm, K0_X_H, K0_X_L, LD_40, g_wh + OFF_WIN, g_wl + OFF_WIN,
                            b_in, nullptr, nullptr, K0_C_H, K0_C_L, LD_136, K0_WS_H, K0_WS_L);
    // conv1 partial: K = first 128 inputs
    gemm_core<2, 128, 64, 256>(acc1, sm, K0_C_H, K0_C_L, LD_136,
                               g_wh + OFF_W1, g_wl + OFF_W1, K0_WS_H, K0_WS_L);
    // WIN second half: w_in rows 128..255 -> C (overwrite)
    gemm2<4, 32, 32, 32, 0>(sm, K0_X_H, K0_X_L, LD_40,
                            g_wh + OFF_WIN + 128 * 32, g_wl + OFF_WIN + 128 * 32,
                            b_in + 128, nullptr, nullptr, K0_C_H, K0_C_L, LD_136, K0_WS_H, K0_WS_L);
    // conv1 partial: K = second 128 inputs (column offset 128 in W1 rows)
    gemm_core<2, 128, 64, 256>(acc1, sm, K0_C_H, K0_C_L, LD_136,
                               g_wh + OFF_W1 + 128, g_wl + OFF_W1 + 128, K0_WS_H, K0_WS_L);
    epilogue_relu<2>(acc1, sm, K0_M_H, K0_M_L, LD_72);

    // conv2: M -> IO (overlays C)
    gemm2<4, 64, 64, 64, 0>(sm, K0_M_H, K0_M_L, LD_72, g_wh + OFF_W2, g_wl + OFF_W2,
                            b2, nullptr, nullptr, K0_IO_H, K0_IO_L, LD_136, K0_WS_H, K0_WS_L);
    __syncthreads();

    store_and_pool(sm, s_cl, 16, b, gfeat, gpool, P0, K0_IO_H, K0_IO_L, LD_136);
}

// ---------------- mid: conv3 (P->Q), conv1 (Q+p2l->P), conv2 (P->Q) ----------------
__global__ void __launch_bounds__(THREADS, 2)
mid_kernel(const unsigned* __restrict__ fin, unsigned* __restrict__ fout,
           const int* __restrict__ cl_in, const int* __restrict__ cl_out,
           int nc_in, float* __restrict__ gpool_out, int nc_out,
           const __nv_bfloat16* __restrict__ wh3, const __nv_bfloat16* __restrict__ wl3,
           const float* __restrict__ b3,
           const __nv_bfloat16* __restrict__ wh1, const __nv_bfloat16* __restrict__ wl1,
           const __nv_bfloat16* __restrict__ wh2, const __nv_bfloat16* __restrict__ wl2,
           const float* __restrict__ b2)
{
    extern __shared__ __nv_bfloat16 sm[];
    int* s_cl = (int*)(sm + MF_END);
    const int tid = threadIdx.x;
    const int P0  = blockIdx.x * TILE;
    const int b   = P0 / NPTS;

    for (int i = tid; i < TILE * 128; i += THREADS) {
        int p = i >> 7, c = i & 127;
        unsigned u = fin[(size_t)(P0 + p) * 128 + c];
        sm[MF_P_H + p * LD_136 + c] = __ushort_as_bfloat16((unsigned short)(u & 0xffff));
        sm[MF_P_L + p * LD_136 + c] = __ushort_as_bfloat16((unsigned short)(u >> 16));
    }
    if (tid < TILE) s_cl[tid] = cl_in[P0 + tid];
    else if (tid < 2 * TILE) s_cl[tid] = cl_out[P0 + tid - TILE];

    const float* p2l_b = g_p2l + b * nc_in * 64;

    gemm2<4, 128, 64, 128, 0>(sm, MF_P_H, MF_P_L, LD_136, wh3, wl3, b3,
                              nullptr, nullptr, MF_Q_H, MF_Q_L, LD_136, MF_WS_H, MF_WS_L);
    gemm2<2, 128, 64, 256, 64>(sm, MF_Q_H, MF_Q_L, LD_136, wh1, wl1, nullptr,
                               p2l_b, s_cl, MF_P_H, MF_P_L, LD_72, MF_WS_H, MF_WS_L);
    gemm2<4, 64, 64, 64, 0>(sm, MF_P_H, MF_P_L, LD_72, wh2, wl2, b2,
                            nullptr, nullptr, MF_Q_H, MF_Q_L, LD_136, MF_WS_H, MF_WS_L);
    __syncthreads();

    store_and_pool(sm, s_cl + TILE, nc_out, b, fout, gpool_out, P0, MF_Q_H, MF_Q_L, LD_136);
}

// ---------------- final: conv3 (P->Q), out1 (Q+p2l->P), out2 (P->max->out) ----------------
__global__ void __launch_bounds__(THREADS, 2)
final_kernel(const unsigned* __restrict__ fin, const int* __restrict__ cl_in,
             const __nv_bfloat16* __restrict__ wh3, const __nv_bfloat16* __restrict__ wl3,
             const float* __restrict__ b3,
             const float* __restrict__ bo2,
             float* __restrict__ out)
{
    extern __shared__ __nv_bfloat16 sm[];
    int* s_cl = (int*)(sm + MF_END);
    const int tid = threadIdx.x;
    const int P0  = blockIdx.x * TILE;
    const int b   = P0 / NPTS;

    for (int i = tid; i < TILE * 128; i += THREADS) {
        int p = i >> 7, c = i & 127;
        unsigned u = fin[(size_t)(P0 + p) * 128 + c];
        sm[MF_P_H + p * LD_136 + c] = __ushort_as_bfloat16((unsigned short)(u & 0xffff));
        sm[MF_P_L + p * LD_136 + c] = __ushort_as_bfloat16((unsigned short)(u >> 16));
    }
    if (tid < TILE) s_cl[tid] = cl_in[P0 + tid];

    const float* p2l_b = g_p2l + b * 64 * 128;

    gemm2<4, 128, 64, 128, 0>(sm, MF_P_H, MF_P_L, LD_136, wh3, wl3, b3,
                              nullptr, nullptr, MF_Q_H, MF_Q_L, LD_136, MF_WS_H, MF_WS_L);
    gemm2<4, 128, 64, 256, 128>(sm, MF_Q_H, MF_Q_L, LD_136, g_wh + OFF_WO1, g_wl + OFF_WO1,
                                nullptr, p2l_b, s_cl, MF_P_H, MF_P_L, LD_136, MF_WS_H, MF_WS_L);
    gemm_out<4, 128, 64, 128>(sm, MF_P_H, MF_P_L, LD_136, g_wh + OFF_WO2, g_wl + OFF_WO2,
                              bo2, out + b * 128, MF_WS_H, MF_WS_L);
}

extern "C" void kernel_launch(void* const* d_in, const int* in_sizes, int n_in,
                              void* d_out, int out_size)
{
    const float* x    = (const float*)d_in[0];
    const int*   cl   = (const int*)  d_in[1];
    const float* w_in = (const float*)d_in[2];
    const float* b_in = (const float*)d_in[3];
    const float* w1   = (const float*)d_in[4];
    const float* b1   = (const float*)d_in[5];
    const float* w2   = (const float*)d_in[6];
    const float* b2   = (const float*)d_in[7];
    const float* w3   = (const float*)d_in[8];
    const float* b3   = (const float*)d_in[9];
    const float* wo1  = (const float*)d_in[10];
    const float* bo1  = (const float*)d_in[11];
    const float* wo2  = (const float*)d_in[12];
    const float* bo2  = (const float*)d_in[13];
    float* out = (float*)d_out;

    void *pa_, *pb_, *pp_, *ph_, *pl_, *pq_;
    cudaGetSymbolAddress(&pa_, g_featA);
    cudaGetSymbolAddress(&pb_, g_featB);
    cudaGetSymbolAddress(&pp_, g_pool);
    cudaGetSymbolAddress(&ph_, g_wh);
    cudaGetSymbolAddress(&pl_, g_wl);
    cudaGetSymbolAddress(&pq_, g_p2l);
    unsigned* fA = (unsigned*)pa_;
    unsigned* fB = (unsigned*)pb_;
    float* pP = (float*)pp_;
    float* pQ = (float*)pq_;
    __nv_bfloat16* wh = (__nv_bfloat16*)ph_;
    __nv_bfloat16* wl = (__nv_bfloat16*)pl_;

    cudaFuncSetAttribute(k0_kernel,    cudaFuncAttributeMaxDynamicSharedMemorySize, SMEM_K0);
    cudaFuncSetAttribute(mid_kernel,   cudaFuncAttributeMaxDynamicSharedMemorySize, SMEM_MF);
    cudaFuncSetAttribute(final_kernel, cudaFuncAttributeMaxDynamicSharedMemorySize, SMEM_MF);

    const int PSTRIDE = BATCH * 64 * 128;

    init_kernel<<<(3 * PSTRIDE + 255) / 256, 256>>>(out);
    convert_all<<<(180224 + 255) / 256, 256>>>(w_in, w1, w2, w3, wo1, wo2);
    warm_kernel<<<1, 32>>>();

    k0_kernel<<<NTILES, THREADS, SMEM_K0>>>(x, cl, b_in, b1, b2, fA, pP);

    p2l_kernel<<<8 * 16, 128>>>(w1 + 1 * 64 * 256, b1 + 64, pP, pQ, 16, 64);
    mid_kernel<<<NTILES, THREADS, SMEM_MF>>>(
        fA, fB, cl, cl + BN, 16, pP + PSTRIDE, 32,
        wh + OFF_W3, wl + OFF_W3, b3,
        wh + OFF_W1 + 64 * 256, wl + OFF_W1 + 64 * 256,
        wh + OFF_W2 + 128 * 64, wl + OFF_W2 + 128 * 64, b2 + 128);

    p2l_kernel<<<8 * 32, 128>>>(w1 + 2 * 64 * 256, b1 + 128, pP + PSTRIDE, pQ, 32, 64);
    mid_kernel<<<NTILES, THREADS, SMEM_MF>>>(
        fB, fA, cl + BN, cl + 2 * BN, 32, pP + 2 * PSTRIDE, 64,
        wh + OFF_W3 + 128 * 128, wl + OFF_W3 + 128 * 128, b3 + 128,
        wh + OFF_W1 + 2 * 64 * 256, wl + OFF_W1 + 2 * 64 * 256,
        wh + OFF_W2 + 2 * 128 * 64, wl + OFF_W2 + 2 * 128 * 64, b2 + 2 * 128);

    p2l_kernel<<<8 * 64, 128>>>(wo1, bo1, pP + 2 * PSTRIDE, pQ, 64, 128);
    final_kernel<<<NTILES, THREADS, SMEM_MF>>>(
        fA, cl + 2 * BN,
        wh + OFF_W3 + 2 * 128 * 128, wl + OFF_W3 + 2 * 128 * 128, b3 + 2 * 128,
        bo2, out);
}